// round 13
// baseline (speedup 1.0000x reference)
#include <cuda_runtime.h>
#include <cuda_bf16.h>
#include <cuda_fp16.h>
#include <mma.h>
#include <math.h>
#include <stdint.h>
#include <type_traits>

using namespace nvcuda;

// ---------------- problem constants ----------------
constexpr int Bsz = 2, S = 1024, D = 512;
constexpr int E = 8;
constexpr int HMOE = 4, HD = 128, HID = 2048;
constexpr int AH = 4, DK = 128;
constexpr int TOK = Bsz * S;              // 2048
constexpr int LTOK = TOK * HMOE;          // 8192
constexpr int LPAIRS = LTOK * 2;          // 16384
constexpr int GPAIRS = TOK * 2;           // 4096
constexpr int CAP = LPAIRS;

// ---------------- scratch (device globals) ------
__device__ float  g_xp[TOK * D];
__device__ float  g_xf[LTOK * HD];
__device__ __half g_H[LPAIRS * HID];           // 64 MB (half)
__device__ float  g_po[LPAIRS * HD];
__device__ float  g_buf1[TOK * D];
__device__ float  g_xl[TOK * D];
__device__ float  g_xn[TOK * D];
__device__ float  g_Q[TOK * D];
__device__ float  g_Kb[TOK * D];
__device__ float  g_V[TOK * D];
__device__ __half g_Sch[Bsz * AH * S * S];     // 16 MB (half scores)
__device__ float  g_O[TOK * D];
__device__ float  g_x1[TOK * D];
__device__ float  g_x2[TOK * D];
__device__ float  g_tw[LPAIRS];
__device__ int    g_lists[E * CAP];
__device__ int    g_counts[E];

// ================= conversion helpers =================
__device__ __forceinline__ void split2p(float a, float b, uint32_t& hi, uint32_t& lo)
{
    __nv_bfloat162 h = __floats2bfloat162_rn(a, b);
    float ra = a - __bfloat162float(h.x);
    float rb = b - __bfloat162float(h.y);
    __nv_bfloat162 l = __floats2bfloat162_rn(ra, rb);
    hi = *(uint32_t*)&h;
    lo = *(uint32_t*)&l;
}
template <int FP16>
__device__ __forceinline__ void cvt2(float a, float b, uint32_t& hi, uint32_t& lo)
{
    if constexpr (FP16) {
        __half2 h = __floats2half2_rn(a, b);
        hi = *(uint32_t*)&h;
        lo = 0;
    } else {
        split2p(a, b, hi, lo);
    }
}
__device__ __forceinline__ float4 ld4(const float* p) { return *(const float4*)p; }
__device__ __forceinline__ float4 ld4(const __half* p)
{
    uint2 r = *(const uint2*)p;
    __half2 h0 = *(__half2*)&r.x, h1 = *(__half2*)&r.y;
    float2 f0 = __half22float2(h0), f1 = __half22float2(h1);
    return make_float4(f0.x, f0.y, f1.x, f1.y);
}

// ================= tile geometry =================
constexpr int BM = 128, BN = 128, BK = 32;
constexpr int LDA  = BK + 8;    // 40
constexpr int LDBT = BK + 8;    // 40
constexpr int LDBN = BN + 8;    // 136
constexpr int LDCs = 64 + 8;    // 72
constexpr int A_ELEMS   = BM * LDA;
constexpr int BT_ELEMS  = BN * LDBT;
constexpr int BNN_ELEMS = BK * LDBN;

constexpr int BMs = 64, BNs = 64;
constexpr int LDAs  = BK + 8;
constexpr int LDBNs = BNs + 8;
constexpr int LDCss = BNs + 8;
constexpr int A_ELs = BMs * LDAs;
constexpr int B_ELs = BK * LDBNs;

constexpr int SMEM_BIG_NT_F16 = 2 * 1 * (A_ELEMS + BT_ELEMS) * 2;
constexpr int SMEM_BIG_NN_F16 = 2 * 1 * (A_ELEMS + BNN_ELEMS) * 2;
constexpr int SMEM_S_SPLIT    = 2 * 2 * (A_ELs + B_ELs) * 2;
constexpr int SMEM_S_F16      = 2 * 1 * (A_ELs + B_ELs) * 2;

// ================= BIG GEMM: 128x128, BK=32, 256 thr =================
template <int TRANSB, int FP16, int AH16, int BH16, int CH16>
__global__ __launch_bounds__(256) void wm_gemm(
    const void* Av, int lda, long aB, long aHo,
    const void* Bv, int ldb, long bB, long bHo,
    const float* bias, long biasH,
    const float* Res,
    void* Cv, int ldc, long cB, long cHo,
    int N, int K, int nH,
    float scale, int relu,
    const int* __restrict__ lists, int cap,
    const int* __restrict__ counts, int rowShift)
{
    using ET  = typename std::conditional<FP16 != 0, __half, __nv_bfloat16>::type;
    using ATy = typename std::conditional<AH16 != 0, const __half, const float>::type;
    using BTy = typename std::conditional<BH16 != 0, const __half, const float>::type;
    using CTy = typename std::conditional<CH16 != 0, __half, float>::type;
    constexpr int NPL = FP16 ? 1 : 2;
    constexpr int B_ELEMS  = TRANSB ? BT_ELEMS : BNN_ELEMS;
    constexpr int BUFBYTES = NPL * (A_ELEMS + B_ELEMS) * 2;

    int z = blockIdx.z, bi = z / nH, hi = z % nH;
    int rowBase = blockIdx.x * BM;
    int colBase = blockIdx.y * BN;
    int Me = 0x7fffffff;
    if (lists) {
        Me = counts[hi];
        if (rowBase >= Me) return;
        lists += (long)hi * cap;
    }
    ATy* A  = (ATy*)Av + (long)bi * aB + (long)hi * aHo;
    BTy* Bm = (BTy*)Bv + (long)bi * bB + (long)hi * bHo;
    CTy* C  = (CTy*)Cv + (long)bi * cB + (long)hi * cHo;
    if (Res)  Res  += (long)bi * cB + (long)hi * cHo;
    if (bias) bias += (long)hi * biasH;

    extern __shared__ __align__(16) char dsm[];
    __shared__ int prs[BM];
    float* Cs = (float*)dsm;

    int tid = threadIdx.x;
    int warp = tid >> 5;
    int wm = warp & 3, wn = warp >> 2;
    int warpM = wm * 32, warpN = wn * 64;

    if (lists) {
        if (tid < BM) prs[tid] = (rowBase + tid < Me) ? lists[rowBase + tid] : -1;
        __syncthreads();
    }

    int nk = K / BK;
    float4 aP[4], bP[4];

    auto loadRegs = [&](int kt) {
        int k0 = kt * BK;
        #pragma unroll
        for (int p = 0; p < 4; p++) {
            int idx = p * 256 + tid;
            int row = idx >> 3, k4 = (idx & 7) * 4;
            if (lists) {
                int pr = prs[row];
                aP[p] = (pr >= 0) ? ld4(A + (long)(pr >> rowShift) * lda + k0 + k4)
                                  : make_float4(0.f, 0.f, 0.f, 0.f);
            } else {
                aP[p] = ld4(A + (long)(rowBase + row) * lda + k0 + k4);
            }
            if (TRANSB) {
                int n = idx >> 3, bk4 = (idx & 7) * 4;
                bP[p] = ld4(Bm + (long)(colBase + n) * ldb + k0 + bk4);
            } else {
                int k = idx >> 5, n4 = (idx & 31) * 4;
                bP[p] = ld4(Bm + (long)(k0 + k) * ldb + colBase + n4);
            }
        }
    };

    auto splitStore = [&](int buf) {
        ET* AsH = (ET*)(dsm + buf * BUFBYTES);
        ET* AsL = AsH + A_ELEMS;
        ET* BsH = AsH + NPL * A_ELEMS;
        ET* BsL = BsH + B_ELEMS;
        #pragma unroll
        for (int p = 0; p < 4; p++) {
            int idx = p * 256 + tid;
            int row = idx >> 3, k4 = (idx & 7) * 4;
            uint32_t h0, l0, h1, l1;
            cvt2<FP16>(aP[p].x, aP[p].y, h0, l0);
            cvt2<FP16>(aP[p].z, aP[p].w, h1, l1);
            *(uint32_t*)&AsH[row * LDA + k4]     = h0;
            *(uint32_t*)&AsH[row * LDA + k4 + 2] = h1;
            if (!FP16) {
                *(uint32_t*)&AsL[row * LDA + k4]     = l0;
                *(uint32_t*)&AsL[row * LDA + k4 + 2] = l1;
            }
            if (TRANSB) {
                int n = idx >> 3, bk4 = (idx & 7) * 4;
                uint32_t bh0, bl0, bh1, bl1;
                cvt2<FP16>(bP[p].x, bP[p].y, bh0, bl0);
                cvt2<FP16>(bP[p].z, bP[p].w, bh1, bl1);
                *(uint32_t*)&BsH[n * LDBT + bk4]     = bh0;
                *(uint32_t*)&BsH[n * LDBT + bk4 + 2] = bh1;
                if (!FP16) {
                    *(uint32_t*)&BsL[n * LDBT + bk4]     = bl0;
                    *(uint32_t*)&BsL[n * LDBT + bk4 + 2] = bl1;
                }
            } else {
                int k = idx >> 5, n4 = (idx & 31) * 4;
                uint32_t bh0, bl0, bh1, bl1;
                cvt2<FP16>(bP[p].x, bP[p].y, bh0, bl0);
                cvt2<FP16>(bP[p].z, bP[p].w, bh1, bl1);
                *(uint32_t*)&BsH[k * LDBN + n4]     = bh0;
                *(uint32_t*)&BsH[k * LDBN + n4 + 2] = bh1;
                if (!FP16) {
                    *(uint32_t*)&BsL[k * LDBN + n4]     = bl0;
                    *(uint32_t*)&BsL[k * LDBN + n4 + 2] = bl1;
                }
            }
        }
    };

    wmma::fragment<wmma::accumulator, 16, 16, 16, float> acc[2][4];
    #pragma unroll
    for (int i = 0; i < 2; i++)
        #pragma unroll
        for (int j = 0; j < 4; j++) wmma::fill_fragment(acc[i][j], 0.f);

    auto compute = [&](int buf) {
        ET* AsH = (ET*)(dsm + buf * BUFBYTES);
        ET* AsL = AsH + A_ELEMS;
        ET* BsH = AsH + NPL * A_ELEMS;
        ET* BsL = BsH + B_ELEMS;
        #pragma unroll
        for (int sub = 0; sub < 2; sub++) {
            int ks = sub * 16;
            wmma::fragment<wmma::matrix_a, 16, 16, 16, ET, wmma::row_major> ah[2], al[2];
            #pragma unroll
            for (int i = 0; i < 2; i++) {
                wmma::load_matrix_sync(ah[i], AsH + (warpM + 16 * i) * LDA + ks, LDA);
                if (!FP16)
                    wmma::load_matrix_sync(al[i], AsL + (warpM + 16 * i) * LDA + ks, LDA);
            }
            if (TRANSB) {
                wmma::fragment<wmma::matrix_b, 16, 16, 16, ET, wmma::col_major> bh, bl;
                #pragma unroll
                for (int j = 0; j < 4; j++) {
                    wmma::load_matrix_sync(bh, BsH + (warpN + 16 * j) * LDBT + ks, LDBT);
                    if (!FP16)
                        wmma::load_matrix_sync(bl, BsL + (warpN + 16 * j) * LDBT + ks, LDBT);
                    #pragma unroll
                    for (int i = 0; i < 2; i++) {
                        wmma::mma_sync(acc[i][j], ah[i], bh, acc[i][j]);
                        if (!FP16) {
                            wmma::mma_sync(acc[i][j], ah[i], bl, acc[i][j]);
                            wmma::mma_sync(acc[i][j], al[i], bh, acc[i][j]);
                        }
                    }
                }
            } else {
                wmma::fragment<wmma::matrix_b, 16, 16, 16, ET, wmma::row_major> bh, bl;
                #pragma unroll
                for (int j = 0; j < 4; j++) {
                    wmma::load_matrix_sync(bh, BsH + ks * LDBN + warpN + 16 * j, LDBN);
                    if (!FP16)
                        wmma::load_matrix_sync(bl, BsL + ks * LDBN + warpN + 16 * j, LDBN);
                    #pragma unroll
                    for (int i = 0; i < 2; i++) {
                        wmma::mma_sync(acc[i][j], ah[i], bh, acc[i][j]);
                        if (!FP16) {
                            wmma::mma_sync(acc[i][j], ah[i], bl, acc[i][j]);
                            wmma::mma_sync(acc[i][j], al[i], bh, acc[i][j]);
                        }
                    }
                }
            }
        }
    };

    loadRegs(0);
    splitStore(0);
    __syncthreads();
    for (int kt = 0; kt < nk; kt++) {
        if (kt + 1 < nk) loadRegs(kt + 1);
        compute(kt & 1);
        if (kt + 1 < nk) splitStore((kt + 1) & 1);
        __syncthreads();
    }

    #pragma unroll
    for (int half = 0; half < 2; half++) {
        if (wn == half) {
            #pragma unroll
            for (int i = 0; i < 2; i++)
                #pragma unroll
                for (int j = 0; j < 4; j++)
                    wmma::store_matrix_sync(Cs + (warpM + 16 * i) * LDCs + 16 * j,
                                            acc[i][j], LDCs, wmma::mem_row_major);
        }
        __syncthreads();
        #pragma unroll
        for (int it = 0; it < 8; it++) {
            int idx = it * 256 + tid;
            int row = idx >> 4;
            int c4 = (idx & 15) * 4;
            long gRow;
            if (lists) {
                int pr = prs[row];
                if (pr < 0) continue;
                gRow = pr;
            } else {
                gRow = rowBase + row;
            }
            float4 v = *(float4*)(Cs + row * LDCs + c4);
            int col = colBase + half * 64 + c4;
            v.x *= scale; v.y *= scale; v.z *= scale; v.w *= scale;
            if (bias) {
                v.x += bias[col]; v.y += bias[col + 1];
                v.z += bias[col + 2]; v.w += bias[col + 3];
            }
            if (Res) {
                const float* rp = Res + gRow * ldc + col;
                v.x += rp[0]; v.y += rp[1]; v.z += rp[2]; v.w += rp[3];
            }
            if (relu) {
                v.x = fmaxf(v.x, 0.f); v.y = fmaxf(v.y, 0.f);
                v.z = fmaxf(v.z, 0.f); v.w = fmaxf(v.w, 0.f);
            }
            if constexpr (CH16) {
                __half2 h0 = __floats2half2_rn(v.x, v.y);
                __half2 h1 = __floats2half2_rn(v.z, v.w);
                *(uint2*)(C + gRow * ldc + col) =
                    make_uint2(*(uint32_t*)&h0, *(uint32_t*)&h1);
            } else {
                *(float4*)(C + gRow * ldc + col) = v;
            }
        }
        __syncthreads();
    }
}

// ================= SMALL GEMM: 64x64, BK=32, 128 thr, NN only ==========
template <int FP16, int AH16, int BH16, int CH16>
__global__ __launch_bounds__(128) void wm_gemm_s(
    const void* Av, int lda, long aB, long aHo,
    const void* Bv, int ldb, long bB, long bHo,
    const float* bias, long biasH,
    const float* Res,
    void* Cv, int ldc, long cB, long cHo,
    int N, int K, int nH,
    float scale, int relu,
    const int* __restrict__ lists, int cap,
    const int* __restrict__ counts, int rowShift)
{
    using ET  = typename std::conditional<FP16 != 0, __half, __nv_bfloat16>::type;
    using ATy = typename std::conditional<AH16 != 0, const __half, const float>::type;
    using BTy = typename std::conditional<BH16 != 0, const __half, const float>::type;
    using CTy = typename std::conditional<CH16 != 0, __half, float>::type;
    constexpr int NPL = FP16 ? 1 : 2;
    constexpr int BUFBYTES = NPL * (A_ELs + B_ELs) * 2;

    int z = blockIdx.z, bi = z / nH, hi = z % nH;
    int rowBase = blockIdx.x * BMs;
    int colBase = blockIdx.y * BNs;
    int Me = 0x7fffffff;
    if (lists) {
        Me = counts[hi];
        if (rowBase >= Me) return;
        lists += (long)hi * cap;
    }
    ATy* A  = (ATy*)Av + (long)bi * aB + (long)hi * aHo;
    BTy* Bm = (BTy*)Bv + (long)bi * bB + (long)hi * bHo;
    CTy* C  = (CTy*)Cv + (long)bi * cB + (long)hi * cHo;
    if (Res)  Res  += (long)bi * cB + (long)hi * cHo;
    if (bias) bias += (long)hi * biasH;

    extern __shared__ __align__(16) char dsm[];
    __shared__ int prs[BMs];
    float* Cs = (float*)dsm;

    int tid = threadIdx.x;
    int warp = tid >> 5;
    int wm = warp & 1, wn = warp >> 1;
    int warpM = wm * 32, warpN = wn * 32;

    if (lists) {
        if (tid < BMs) prs[tid] = (rowBase + tid < Me) ? lists[rowBase + tid] : -1;
        __syncthreads();
    }

    int nk = K / BK;
    float4 aP[4], bP[4];

    auto loadRegs = [&](int kt) {
        int k0 = kt * BK;
        #pragma unroll
        for (int p = 0; p < 4; p++) {
            int idx = p * 128 + tid;
            int row = idx >> 3, k4 = (idx & 7) * 4;
            if (lists) {
                int pr = prs[row];
                aP[p] = (pr >= 0) ? ld4(A + (long)(pr >> rowShift) * lda + k0 + k4)
                                  : make_float4(0.f, 0.f, 0.f, 0.f);
            } else {
                aP[p] = ld4(A + (long)(rowBase + row) * lda + k0 + k4);
            }
            int k = idx >> 4, n4 = (idx & 15) * 4;
            bP[p] = ld4(Bm + (long)(k0 + k) * ldb + colBase + n4);
        }
    };

    auto splitStore = [&](int buf) {
        ET* AsH = (ET*)(dsm + buf * BUFBYTES);
        ET* AsL = AsH + A_ELs;
        ET* BsH = AsH + NPL * A_ELs;
        ET* BsL = BsH + B_ELs;
        #pragma unroll
        for (int p = 0; p < 4; p++) {
            int idx = p * 128 + tid;
            int row = idx >> 3, k4 = (idx & 7) * 4;
            uint32_t h0, l0, h1, l1;
            cvt2<FP16>(aP[p].x, aP[p].y, h0, l0);
            cvt2<FP16>(aP[p].z, aP[p].w, h1, l1);
            *(uint32_t*)&AsH[row * LDAs + k4]     = h0;
            *(uint32_t*)&AsH[row * LDAs + k4 + 2] = h1;
            if (!FP16) {
                *(uint32_t*)&AsL[row * LDAs + k4]     = l0;
                *(uint32_t*)&AsL[row * LDAs + k4 + 2] = l1;
            }
            int k = idx >> 4, n4 = (idx & 15) * 4;
            uint32_t bh0, bl0, bh1, bl1;
            cvt2<FP16>(bP[p].x, bP[p].y, bh0, bl0);
            cvt2<FP16>(bP[p].z, bP[p].w, bh1, bl1);
            *(uint32_t*)&BsH[k * LDBNs + n4]     = bh0;
            *(uint32_t*)&BsH[k * LDBNs + n4 + 2] = bh1;
            if (!FP16) {
                *(uint32_t*)&BsL[k * LDBNs + n4]     = bl0;
                *(uint32_t*)&BsL[k * LDBNs + n4 + 2] = bl1;
            }
        }
    };

    wmma::fragment<wmma::accumulator, 16, 16, 16, float> acc[2][2];
    #pragma unroll
    for (int i = 0; i < 2; i++)
        #pragma unroll
        for (int j = 0; j < 2; j++) wmma::fill_fragment(acc[i][j], 0.f);

    auto compute = [&](int buf) {
        ET* AsH = (ET*)(dsm + buf * BUFBYTES);
        ET* AsL = AsH + A_ELs;
        ET* BsH = AsH + NPL * A_ELs;
        ET* BsL = BsH + B_ELs;
        #pragma unroll
        for (int sub = 0; sub < 2; sub++) {
            int ks = sub * 16;
            wmma::fragment<wmma::matrix_a, 16, 16, 16, ET, wmma::row_major> ah[2], al[2];
            #pragma unroll
            for (int i = 0; i < 2; i++) {
                wmma::load_matrix_sync(ah[i], AsH + (warpM + 16 * i) * LDAs + ks, LDAs);
                if (!FP16)
                    wmma::load_matrix_sync(al[i], AsL + (warpM + 16 * i) * LDAs + ks, LDAs);
            }
            wmma::fragment<wmma::matrix_b, 16, 16, 16, ET, wmma::row_major> bh, bl;
            #pragma unroll
            for (int j = 0; j < 2; j++) {
                wmma::load_matrix_sync(bh, BsH + ks * LDBNs + warpN + 16 * j, LDBNs);
                if (!FP16)
                    wmma::load_matrix_sync(bl, BsL + ks * LDBNs + warpN + 16 * j, LDBNs);
                #pragma unroll
                for (int i = 0; i < 2; i++) {
                    wmma::mma_sync(acc[i][j], ah[i], bh, acc[i][j]);
                    if (!FP16) {
                        wmma::mma_sync(acc[i][j], ah[i], bl, acc[i][j]);
                        wmma::mma_sync(acc[i][j], al[i], bh, acc[i][j]);
                    }
                }
            }
        }
    };

    loadRegs(0);
    splitStore(0);
    __syncthreads();
    for (int kt = 0; kt < nk; kt++) {
        if (kt + 1 < nk) loadRegs(kt + 1);
        compute(kt & 1);
        if (kt + 1 < nk) splitStore((kt + 1) & 1);
        __syncthreads();
    }

    #pragma unroll
    for (int i = 0; i < 2; i++)
        #pragma unroll
        for (int j = 0; j < 2; j++)
            wmma::store_matrix_sync(Cs + (warpM + 16 * i) * LDCss + warpN + 16 * j,
                                    acc[i][j], LDCss, wmma::mem_row_major);
    __syncthreads();
    #pragma unroll
    for (int it = 0; it < 8; it++) {
        int idx = it * 128 + tid;
        int row = idx >> 4;
        int c4 = (idx & 15) * 4;
        long gRow;
        if (lists) {
            int pr = prs[row];
            if (pr < 0) continue;
            gRow = pr;
        } else {
            gRow = rowBase + row;
        }
        float4 v = *(float4*)(Cs + row * LDCss + c4);
        int col = colBase + c4;
        v.x *= scale; v.y *= scale; v.z *= scale; v.w *= scale;
        if (bias) {
            v.x += bias[col]; v.y += bias[col + 1];
            v.z += bias[col + 2]; v.w += bias[col + 3];
        }
        if (Res) {
            const float* rp = Res + gRow * ldc + col;
            v.x += rp[0]; v.y += rp[1]; v.z += rp[2]; v.w += rp[3];
        }
        if (relu) {
            v.x = fmaxf(v.x, 0.f); v.y = fmaxf(v.y, 0.f);
            v.z = fmaxf(v.z, 0.f); v.w = fmaxf(v.w, 0.f);
        }
        if constexpr (CH16) {
            __half2 h0 = __floats2half2_rn(v.x, v.y);
            __half2 h1 = __floats2half2_rn(v.z, v.w);
            *(uint2*)(C + gRow * ldc + col) =
                make_uint2(*(uint32_t*)&h0, *(uint32_t*)&h1);
        } else {
            *(float4*)(C + gRow * ldc + col) = v;
        }
    }
}

// ---------------- gate + softmax + top-2 + scatter ----------------
template <int KD>
__global__ void gate_topk(
    const float* __restrict__ X, const float* __restrict__ GW,
    const float* __restrict__ GB, float* __restrict__ tw,
    int* __restrict__ lists, int* __restrict__ counts, int cap, int T)
{
    int warp = (blockIdx.x * blockDim.x + threadIdx.x) >> 5;
    int lane = threadIdx.x & 31;
    if (warp >= T) return;
    const float* x = X + (long)warp * KD;
    float xv[KD / 32];
#pragma unroll
    for (int i = 0; i < KD / 32; i++) xv[i] = x[lane + 32 * i];
    float p[E] = {0.f, 0.f, 0.f, 0.f, 0.f, 0.f, 0.f, 0.f};
#pragma unroll
    for (int i = 0; i < KD / 32; i++) {
        float xvi = xv[i];
        const float4* g = (const float4*)(GW + (long)(lane + 32 * i) * E);
        float4 a = g[0], b4 = g[1];
        p[0] += xvi * a.x;  p[1] += xvi * a.y;
        p[2] += xvi * a.z;  p[3] += xvi * a.w;
        p[4] += xvi * b4.x; p[5] += xvi * b4.y;
        p[6] += xvi * b4.z; p[7] += xvi * b4.w;
    }
#pragma unroll
    for (int e = 0; e < E; e++) {
#pragma unroll
        for (int o = 16; o > 0; o >>= 1) p[e] += __shfl_xor_sync(0xffffffffu, p[e], o);
        p[e] += GB[e];
    }
    float m = p[0];
#pragma unroll
    for (int e = 1; e < E; e++) m = fmaxf(m, p[e]);
    float sum = 0.f;
#pragma unroll
    for (int e = 0; e < E; e++) { p[e] = expf(p[e] - m); sum += p[e]; }
    float inv = 1.f / sum;
#pragma unroll
    for (int e = 0; e < E; e++) p[e] *= inv;
    float v0 = -1e30f; int i0 = 0;
#pragma unroll
    for (int e = 0; e < E; e++) if (p[e] > v0) { v0 = p[e]; i0 = e; }
    float v1 = -1e30f; int i1 = 0;
#pragma unroll
    for (int e = 0; e < E; e++) if (e != i0 && p[e] > v1) { v1 = p[e]; i1 = e; }
    float e0 = expf(v0), e1 = expf(v1);
    float wi = 1.f / (e0 + e1);
    if (lane == 0) {
        tw[warp * 2 + 0] = e0 * wi;
        tw[warp * 2 + 1] = e1 * wi;
        int pos0 = atomicAdd(&counts[i0], 1);
        lists[i0 * cap + pos0] = warp * 2;
        int pos1 = atomicAdd(&counts[i1], 1);
        lists[i1 * cap + pos1] = warp * 2 + 1;
    }
}

// ---------------- layernorm (D=512, block=256) ----------------
__global__ void layernorm_k(const float* __restrict__ X,
                            const float* __restrict__ w,
                            const float* __restrict__ b,
                            float* __restrict__ Y)
{
    int row = blockIdx.x;
    const float* x = X + (long)row * D;
    float* y = Y + (long)row * D;
    int tid = threadIdx.x;
    float x0 = x[tid], x1 = x[tid + 256];
    __shared__ float red[256];
    red[tid] = x0 + x1;
    __syncthreads();
    for (int o = 128; o > 0; o >>= 1) { if (tid < o) red[tid] += red[tid + o]; __syncthreads(); }
    float mu = red[0] * (1.f / D);
    __syncthreads();
    float d0 = x0 - mu, d1 = x1 - mu;
    red[tid] = d0 * d0 + d1 * d1;
    __syncthreads();
    for (int o = 128; o > 0; o >>= 1) { if (tid < o) red[tid] += red[tid + o]; __syncthreads(); }
    float rs = rsqrtf(red[0] * (1.f / D) + 1e-12f);
    y[tid]       = d0 * rs * w[tid]       + b[tid];
    y[tid + 256] = d1 * rs * w[tid + 256] + b[tid + 256];
}

// ---------------- row softmax on half scores ----------------
__global__ void softmax_rows_h(__half* __restrict__ Sm)
{
    __half* s = Sm + (long)blockIdx.x * S;
    int tid = threadIdx.x;
    float v[4];
#pragma unroll
    for (int i = 0; i < 4; i++) v[i] = __half2float(s[tid + 256 * i]);
    __shared__ float red[256];
    float m = fmaxf(fmaxf(v[0], v[1]), fmaxf(v[2], v[3]));
    red[tid] = m;
    __syncthreads();
    for (int o = 128; o > 0; o >>= 1) { if (tid < o) red[tid] = fmaxf(red[tid], red[tid + o]); __syncthreads(); }
    m = red[0];
    __syncthreads();
    float t = 0.f;
#pragma unroll
    for (int i = 0; i < 4; i++) { v[i] = expf(v[i] - m); t += v[i]; }
    red[tid] = t;
    __syncthreads();
    for (int o = 128; o > 0; o >>= 1) { if (tid < o) red[tid] += red[tid + o]; __syncthreads(); }
    float inv = 1.f / red[0];
#pragma unroll
    for (int i = 0; i < 4; i++) s[tid + 256 * i] = __float2half(v[i] * inv);
}

// ---------------- small elementwise kernels ----------------
__global__ void zero_counts() { if (threadIdx.x < E) g_counts[threadIdx.x] = 0; }

__global__ void copy_xf()
{
    int idx = blockIdx.x * blockDim.x + threadIdx.x;
    int t = idx >> 7, c = idx & 127;
    int bb = t >> 12, h = (t >> 10) & 3, s = t & 1023;
    g_xf[idx] = g_xp[((long)(bb * S + s)) * D + h * HD + c];
}

__global__ void combine_local()
{
    int idx = blockIdx.x * blockDim.x + threadIdx.x;
    int t = idx >> 7, c = idx & 127;
    float v = g_xf[idx]
            + g_tw[2 * t]     * g_po[(long)(2 * t) * HD + c]
            + g_tw[2 * t + 1] * g_po[(long)(2 * t + 1) * HD + c];
    int bb = t >> 12, h = (t >> 10) & 3, s = t & 1023;
    g_buf1[((long)(bb * S + s)) * D + h * HD + c] = v;
}

__global__ void final_combine(float* __restrict__ out)
{
    int idx = blockIdx.x * blockDim.x + threadIdx.x;
    int t = idx >> 9, c = idx & 511;
    out[idx] = g_x1[idx]
             + g_tw[2 * t]     * g_po[(long)(2 * t) * D + c]
             + g_tw[2 * t + 1] * g_po[(long)(2 * t + 1) * D + c];
}

// ---------------- launch ----------------
extern "C" void kernel_launch(void* const* d_in, const int* in_sizes, int n_in,
                              void* d_out, int out_size)
{
    const float* x       = (const float*)d_in[0];
    const float* pre_w   = (const float*)d_in[1];
    const float* pre_b   = (const float*)d_in[2];
    const float* l_gw    = (const float*)d_in[3];
    const float* l_gb    = (const float*)d_in[4];
    const float* l_w1    = (const float*)d_in[5];
    const float* l_b1    = (const float*)d_in[6];
    const float* l_w2    = (const float*)d_in[7];
    const float* l_b2    = (const float*)d_in[8];
    const float* align_w = (const float*)d_in[9];
    const float* align_b = (const float*)d_in[10];
    const float* ln1_w   = (const float*)d_in[11];
    const float* ln1_b   = (const float*)d_in[12];
    const float* wq      = (const float*)d_in[13];
    const float* bq      = (const float*)d_in[14];
    const float* wk      = (const float*)d_in[15];
    const float* bk      = (const float*)d_in[16];
    const float* wv      = (const float*)d_in[17];
    const float* bv      = (const float*)d_in[18];
    const float* wo      = (const float*)d_in[19];
    const float* bo      = (const float*)d_in[20];
    const float* ln2_w   = (const float*)d_in[21];
    const float* ln2_b   = (const float*)d_in[22];
    const float* g_gw    = (const float*)d_in[23];
    const float* g_gb    = (const float*)d_in[24];
    const float* gw1     = (const float*)d_in[25];
    const float* gb1     = (const float*)d_in[26];
    const float* gw2     = (const float*)d_in[27];
    const float* gb2     = (const float*)d_in[28];
    float* out = (float*)d_out;

    float *xp, *xf, *po, *buf1, *xl, *xn, *Q, *Kb, *V, *O, *x1, *x2, *tw;
    __half *H, *Sch;
    int *lists, *counts;
    cudaGetSymbolAddress((void**)&xp, g_xp);
    cudaGetSymbolAddress((void**)&xf, g_xf);
    cudaGetSymbolAddress((void**)&H, g_H);
    cudaGetSymbolAddress((void**)&po, g_po);
    cudaGetSymbolAddress((void**)&buf1, g_buf1);
    cudaGetSymbolAddress((void**)&xl, g_xl);
    cudaGetSymbolAddress((void**)&xn, g_xn);
    cudaGetSymbolAddress((void**)&Q, g_Q);
    cudaGetSymbolAddress((void**)&Kb, g_Kb);
    cudaGetSymbolAddress((void**)&V, g_V);
    cudaGetSymbolAddress((void**)&Sch, g_Sch);
    cudaGetSymbolAddress((void**)&O, g_O);
    cudaGetSymbolAddress((void**)&x1, g_x1);
    cudaGetSymbolAddress((void**)&x2, g_x2);
    cudaGetSymbolAddress((void**)&tw, g_tw);
    cudaGetSymbolAddress((void**)&lists, g_lists);
    cudaGetSymbolAddress((void**)&counts, g_counts);

    cudaFuncSetAttribute(wm_gemm<1,1,0,0,1>, cudaFuncAttributeMaxDynamicSharedMemorySize, SMEM_BIG_NT_F16);
    cudaFuncSetAttribute(wm_gemm<0,1,0,0,1>, cudaFuncAttributeMaxDynamicSharedMemorySize, SMEM_BIG_NN_F16);
    cudaFuncSetAttribute(wm_gemm<0,1,1,0,0>, cudaFuncAttributeMaxDynamicSharedMemorySize, SMEM_BIG_NN_F16);
    cudaFuncSetAttribute(wm_gemm_s<0,0,0,0>, cudaFuncAttributeMaxDynamicSharedMemorySize, SMEM_S_SPLIT);
    cudaFuncSetAttribute(wm_gemm_s<1,0,0,0>, cudaFuncAttributeMaxDynamicSharedMemorySize, SMEM_S_F16);
    cudaFuncSetAttribute(wm_gemm_s<1,1,0,0>, cudaFuncAttributeMaxDynamicSharedMemorySize, SMEM_S_F16);

    const float rscale = 0.08838834764831845f;  // 1/sqrt(128)

    // 1. xp = x @ pre_w + pre_b  (split-bf16: feeds local gate top-2)
    wm_gemm_s<0,0,0,0><<<dim3(TOK / BMs, D / BNs, 1), 128, SMEM_S_SPLIT>>>(
        x, D, 0, 0, pre_w, D, 0, 0, pre_b, 0, nullptr,
        xp, D, 0, 0, D, D, 1, 1.f, 0, nullptr, 0, nullptr, 0);

    // 2. reshape to local sub-tokens
    copy_xf<<<LTOK * HD / 256, 256>>>();

    // 3-4. local gate + top2
    zero_counts<<<1, 32>>>();
    gate_topk<HD><<<LTOK / 4, 128>>>(xf, l_gw, l_gb, tw, lists, counts, CAP, LTOK);

    // 5. H = relu(xf @ l_w1 + b1)  (fp16 compute, fp32 weights, C half)
    wm_gemm<0,1,0,0,1><<<dim3(LPAIRS / BM, HID / BN, E), 256, SMEM_BIG_NN_F16>>>(
        xf, HD, 0, 0, l_w1, HID, 0, (long)HD * HID, l_b1, HID, nullptr,
        H, HID, 0, 0, HID, HD, E, 1.f, 1, lists, CAP, counts, 1);

    // 6. po = H @ l_w2 + b2  (big tile: 4x fewer B re-reads; A half)
    wm_gemm<0,1,1,0,0><<<dim3(LPAIRS / BM, HD / BN, E), 256, SMEM_BIG_NN_F16>>>(
        H, HID, 0, 0, l_w2, HD, 0, (long)HID * HD, l_b2, HD, nullptr,
        po, HD, 0, 0, HD, HID, E, 1.f, 0, lists, CAP, counts, 0);

    // 7. xf + weighted expert out -> [b,s,d]
    combine_local<<<LTOK * HD / 256, 256>>>();

    // 8. align projection (fp16)
    wm_gemm_s<1,0,0,0><<<dim3(TOK / BMs, D / BNs, 1), 128, SMEM_S_F16>>>(
        buf1, D, 0, 0, align_w, D, 0, 0, align_b, 0, nullptr,
        xl, D, 0, 0, D, D, 1, 1.f, 0, nullptr, 0, nullptr, 0);

    // 9. ln1
    layernorm_k<<<TOK, 256>>>(xl, ln1_w, ln1_b, xn);

    // 10-12. Q,K,V projections (fp16)
    wm_gemm_s<1,0,0,0><<<dim3(TOK / BMs, D / BNs, 1), 128, SMEM_S_F16>>>(
        xn, D, 0, 0, wq, D, 0, 0, bq, 0, nullptr,
        Q, D, 0, 0, D, D, 1, 1.f, 0, nullptr, 0, nullptr, 0);
    wm_gemm_s<1,0,0,0><<<dim3(TOK / BMs, D / BNs, 1), 128, SMEM_S_F16>>>(
        xn, D, 0, 0, wk, D, 0, 0, bk, 0, nullptr,
        Kb, D, 0, 0, D, D, 1, 1.f, 0, nullptr, 0, nullptr, 0);
    wm_gemm_s<1,0,0,0><<<dim3(TOK / BMs, D / BNs, 1), 128, SMEM_S_F16>>>(
        xn, D, 0, 0, wv, D, 0, 0, bv, 0, nullptr,
        V, D, 0, 0, D, D, 1, 1.f, 0, nullptr, 0, nullptr, 0);

    // 13. scores = Q @ K^T / sqrt(DK)  (NT fp16, C half)
    wm_gemm<1,1,0,0,1><<<dim3(S / BM, S / BN, Bsz * AH), 256, SMEM_BIG_NT_F16>>>(
        Q, D, (long)S * D, DK, Kb, D, (long)S * D, DK, nullptr, 0, nullptr,
        Sch, S, (long)AH * S * S, (long)S * S,
        S, DK, AH, rscale, 0, nullptr, 0, nullptr, 0);

    // 14. softmax rows (half)
    softmax_rows_h<<<Bsz * AH * S, 256>>>(Sch);

    // 15. O = P @ V  (A half)
    wm_gemm_s<1,1,0,0><<<dim3(S / BMs, DK / BNs, Bsz * AH), 128, SMEM_S_F16>>>(
        Sch, S, (long)AH * S * S, (long)S * S,
        V, D, (long)S * D, DK, nullptr, 0, nullptr,
        O, D, (long)S * D, DK, DK, S, AH, 1.f, 0, nullptr, 0, nullptr, 0);

    // 16. x1 = x + O @ wo + bo  (fp16)
    wm_gemm_s<1,0,0,0><<<dim3(TOK / BMs, D / BNs, 1), 128, SMEM_S_F16>>>(
        O, D, 0, 0, wo, D, 0, 0, bo, 0, x,
        x1, D, 0, 0, D, D, 1, 1.f, 0, nullptr, 0, nullptr, 0);

    // 17. ln2
    layernorm_k<<<TOK, 256>>>(x1, ln2_w, ln2_b, x2);

    // 18-19. global gate + top2
    zero_counts<<<1, 32>>>();
    gate_topk<D><<<TOK / 4, 128>>>(x2, g_gw, g_gb, tw, lists, counts, CAP, TOK);

    // 20. H = relu(x2 @ gw1 + b1)  (fp16 compute, fp32 weights, C half)
    wm_gemm<0,1,0,0,1><<<dim3(GPAIRS / BM, HID / BN, E), 256, SMEM_BIG_NN_F16>>>(
        x2, D, 0, 0, gw1, HID, 0, (long)D * HID, gb1, HID, nullptr,
        H, HID, 0, 0, HID, D, E, 1.f, 1, lists, CAP, counts, 1);

    // 21. po = H @ gw2 + b2  (big tile; A half)
    wm_gemm<0,1,1,0,0><<<dim3(GPAIRS / BM, D / BN, E), 256, SMEM_BIG_NN_F16>>>(
        H, HID, 0, 0, gw2, D, 0, (long)HID * D, gb2, D, nullptr,
        po, D, 0, 0, D, HID, E, 1.f, 0, lists, CAP, counts, 0);

    // 22. out = x1 + weighted expert out
    final_combine<<<TOK * D / 256, 256>>>(out);
}

// round 14
// speedup vs baseline: 1.1467x; 1.1467x over previous
#include <cuda_runtime.h>
#include <cuda_bf16.h>
#include <cuda_fp16.h>
#include <mma.h>
#include <math.h>
#include <stdint.h>
#include <type_traits>

using namespace nvcuda;

// ---------------- problem constants ----------------
constexpr int Bsz = 2, S = 1024, D = 512;
constexpr int E = 8;
constexpr int HMOE = 4, HD = 128, HID = 2048;
constexpr int AH = 4, DK = 128;
constexpr int TOK = Bsz * S;              // 2048
constexpr int LTOK = TOK * HMOE;          // 8192
constexpr int LPAIRS = LTOK * 2;          // 16384
constexpr int GPAIRS = TOK * 2;           // 4096
constexpr int CAP = LPAIRS;
constexpr int D3 = 3 * D;                 // 1536 (QKV fused)

// ---------------- scratch (device globals) ------
__device__ float  g_xp[TOK * D];
__device__ float  g_xf[LTOK * HD];
__device__ __half g_H[LPAIRS * HID];           // half
__device__ float  g_po[LPAIRS * HD];
__device__ float  g_buf1[TOK * D];
__device__ float  g_xl[TOK * D];
__device__ float  g_xn[TOK * D];
__device__ float  g_QKV[TOK * D3];             // packed Q|K|V
__device__ __half g_Sch[Bsz * AH * S * S];     // half scores
__device__ float  g_O[TOK * D];
__device__ float  g_x1[TOK * D];
__device__ float  g_x2[TOK * D];
__device__ float  g_tw[LPAIRS];
__device__ int    g_lists[E * CAP];
__device__ int    g_counts[E];
__device__ float  g_wqkv[D * D3];
__device__ float  g_bqkv[D3];

// ================= conversion helpers =================
__device__ __forceinline__ void split2p(float a, float b, uint32_t& hi, uint32_t& lo)
{
    __nv_bfloat162 h = __floats2bfloat162_rn(a, b);
    float ra = a - __bfloat162float(h.x);
    float rb = b - __bfloat162float(h.y);
    __nv_bfloat162 l = __floats2bfloat162_rn(ra, rb);
    hi = *(uint32_t*)&h;
    lo = *(uint32_t*)&l;
}
template <int FP16>
__device__ __forceinline__ void cvt2(float a, float b, uint32_t& hi, uint32_t& lo)
{
    if constexpr (FP16) {
        __half2 h = __floats2half2_rn(a, b);
        hi = *(uint32_t*)&h;
        lo = 0;
    } else {
        split2p(a, b, hi, lo);
    }
}
__device__ __forceinline__ float4 ld4(const float* p) { return *(const float4*)p; }
__device__ __forceinline__ float4 ld4(const __half* p)
{
    uint2 r = *(const uint2*)p;
    __half2 h0 = *(__half2*)&r.x, h1 = *(__half2*)&r.y;
    float2 f0 = __half22float2(h0), f1 = __half22float2(h1);
    return make_float4(f0.x, f0.y, f1.x, f1.y);
}

// ================= tile geometry =================
constexpr int BM = 128, BN = 128, BK = 32;
constexpr int LDA  = BK + 8;    // 40
constexpr int LDBT = BK + 8;    // 40
constexpr int LDBN = BN + 8;    // 136
constexpr int LDCs = 64 + 8;    // 72
constexpr int A_ELEMS   = BM * LDA;
constexpr int BT_ELEMS  = BN * LDBT;
constexpr int BNN_ELEMS = BK * LDBN;

constexpr int BMs = 64, BNs = 64;
constexpr int LDAs  = BK + 8;
constexpr int LDBNs = BNs + 8;
constexpr int LDCss = BNs + 8;
constexpr int A_ELs = BMs * LDAs;
constexpr int B_ELs = BK * LDBNs;

constexpr int SMEM_BIG_NT_F16 = 2 * 1 * (A_ELEMS + BT_ELEMS) * 2;
constexpr int SMEM_BIG_NN_F16 = 2 * 1 * (A_ELEMS + BNN_ELEMS) * 2;
constexpr int SMEM_S_SPLIT    = 2 * 2 * (A_ELs + B_ELs) * 2;
constexpr int SMEM_S_F16      = 2 * 1 * (A_ELs + B_ELs) * 2;

// ================= BIG GEMM: 128x128, BK=32, 256 thr =================
template <int TRANSB, int FP16, int AH16, int BH16, int CH16>
__global__ __launch_bounds__(256) void wm_gemm(
    const void* Av, int lda, long aB, long aHo,
    const void* Bv, int ldb, long bB, long bHo,
    const float* bias, long biasH,
    const float* Res,
    void* Cv, int ldc, long cB, long cHo,
    int N, int K, int nH,
    float scale, int relu,
    const int* __restrict__ lists, int cap,
    const int* __restrict__ counts, int rowShift)
{
    using ET  = typename std::conditional<FP16 != 0, __half, __nv_bfloat16>::type;
    using ATy = typename std::conditional<AH16 != 0, const __half, const float>::type;
    using BTy = typename std::conditional<BH16 != 0, const __half, const float>::type;
    using CTy = typename std::conditional<CH16 != 0, __half, float>::type;
    constexpr int NPL = FP16 ? 1 : 2;
    constexpr int B_ELEMS  = TRANSB ? BT_ELEMS : BNN_ELEMS;
    constexpr int BUFBYTES = NPL * (A_ELEMS + B_ELEMS) * 2;

    int z = blockIdx.z, bi = z / nH, hi = z % nH;
    int rowBase = blockIdx.x * BM;
    int colBase = blockIdx.y * BN;
    int Me = 0x7fffffff;
    if (lists) {
        Me = counts[hi];
        if (rowBase >= Me) return;
        lists += (long)hi * cap;
    }
    ATy* A  = (ATy*)Av + (long)bi * aB + (long)hi * aHo;
    BTy* Bm = (BTy*)Bv + (long)bi * bB + (long)hi * bHo;
    CTy* C  = (CTy*)Cv + (long)bi * cB + (long)hi * cHo;
    if (Res)  Res  += (long)bi * cB + (long)hi * cHo;
    if (bias) bias += (long)hi * biasH;

    extern __shared__ __align__(16) char dsm[];
    __shared__ int prs[BM];
    float* Cs = (float*)dsm;

    int tid = threadIdx.x;
    int warp = tid >> 5;
    int wm = warp & 3, wn = warp >> 2;
    int warpM = wm * 32, warpN = wn * 64;

    if (lists) {
        if (tid < BM) prs[tid] = (rowBase + tid < Me) ? lists[rowBase + tid] : -1;
        __syncthreads();
    }

    int nk = K / BK;
    float4 aP[4], bP[4];

    auto loadRegs = [&](int kt) {
        int k0 = kt * BK;
        #pragma unroll
        for (int p = 0; p < 4; p++) {
            int idx = p * 256 + tid;
            int row = idx >> 3, k4 = (idx & 7) * 4;
            if (lists) {
                int pr = prs[row];
                aP[p] = (pr >= 0) ? ld4(A + (long)(pr >> rowShift) * lda + k0 + k4)
                                  : make_float4(0.f, 0.f, 0.f, 0.f);
            } else {
                aP[p] = ld4(A + (long)(rowBase + row) * lda + k0 + k4);
            }
            if (TRANSB) {
                int n = idx >> 3, bk4 = (idx & 7) * 4;
                bP[p] = ld4(Bm + (long)(colBase + n) * ldb + k0 + bk4);
            } else {
                int k = idx >> 5, n4 = (idx & 31) * 4;
                bP[p] = ld4(Bm + (long)(k0 + k) * ldb + colBase + n4);
            }
        }
    };

    auto splitStore = [&](int buf) {
        ET* AsH = (ET*)(dsm + buf * BUFBYTES);
        ET* AsL = AsH + A_ELEMS;
        ET* BsH = AsH + NPL * A_ELEMS;
        ET* BsL = BsH + B_ELEMS;
        #pragma unroll
        for (int p = 0; p < 4; p++) {
            int idx = p * 256 + tid;
            int row = idx >> 3, k4 = (idx & 7) * 4;
            uint32_t h0, l0, h1, l1;
            cvt2<FP16>(aP[p].x, aP[p].y, h0, l0);
            cvt2<FP16>(aP[p].z, aP[p].w, h1, l1);
            *(uint32_t*)&AsH[row * LDA + k4]     = h0;
            *(uint32_t*)&AsH[row * LDA + k4 + 2] = h1;
            if (!FP16) {
                *(uint32_t*)&AsL[row * LDA + k4]     = l0;
                *(uint32_t*)&AsL[row * LDA + k4 + 2] = l1;
            }
            if (TRANSB) {
                int n = idx >> 3, bk4 = (idx & 7) * 4;
                uint32_t bh0, bl0, bh1, bl1;
                cvt2<FP16>(bP[p].x, bP[p].y, bh0, bl0);
                cvt2<FP16>(bP[p].z, bP[p].w, bh1, bl1);
                *(uint32_t*)&BsH[n * LDBT + bk4]     = bh0;
                *(uint32_t*)&BsH[n * LDBT + bk4 + 2] = bh1;
                if (!FP16) {
                    *(uint32_t*)&BsL[n * LDBT + bk4]     = bl0;
                    *(uint32_t*)&BsL[n * LDBT + bk4 + 2] = bl1;
                }
            } else {
                int k = idx >> 5, n4 = (idx & 31) * 4;
                uint32_t bh0, bl0, bh1, bl1;
                cvt2<FP16>(bP[p].x, bP[p].y, bh0, bl0);
                cvt2<FP16>(bP[p].z, bP[p].w, bh1, bl1);
                *(uint32_t*)&BsH[k * LDBN + n4]     = bh0;
                *(uint32_t*)&BsH[k * LDBN + n4 + 2] = bh1;
                if (!FP16) {
                    *(uint32_t*)&BsL[k * LDBN + n4]     = bl0;
                    *(uint32_t*)&BsL[k * LDBN + n4 + 2] = bl1;
                }
            }
        }
    };

    wmma::fragment<wmma::accumulator, 16, 16, 16, float> acc[2][4];
    #pragma unroll
    for (int i = 0; i < 2; i++)
        #pragma unroll
        for (int j = 0; j < 4; j++) wmma::fill_fragment(acc[i][j], 0.f);

    auto compute = [&](int buf) {
        ET* AsH = (ET*)(dsm + buf * BUFBYTES);
        ET* AsL = AsH + A_ELEMS;
        ET* BsH = AsH + NPL * A_ELEMS;
        ET* BsL = BsH + B_ELEMS;
        #pragma unroll
        for (int sub = 0; sub < 2; sub++) {
            int ks = sub * 16;
            wmma::fragment<wmma::matrix_a, 16, 16, 16, ET, wmma::row_major> ah[2], al[2];
            #pragma unroll
            for (int i = 0; i < 2; i++) {
                wmma::load_matrix_sync(ah[i], AsH + (warpM + 16 * i) * LDA + ks, LDA);
                if (!FP16)
                    wmma::load_matrix_sync(al[i], AsL + (warpM + 16 * i) * LDA + ks, LDA);
            }
            if (TRANSB) {
                wmma::fragment<wmma::matrix_b, 16, 16, 16, ET, wmma::col_major> bh, bl;
                #pragma unroll
                for (int j = 0; j < 4; j++) {
                    wmma::load_matrix_sync(bh, BsH + (warpN + 16 * j) * LDBT + ks, LDBT);
                    if (!FP16)
                        wmma::load_matrix_sync(bl, BsL + (warpN + 16 * j) * LDBT + ks, LDBT);
                    #pragma unroll
                    for (int i = 0; i < 2; i++) {
                        wmma::mma_sync(acc[i][j], ah[i], bh, acc[i][j]);
                        if (!FP16) {
                            wmma::mma_sync(acc[i][j], ah[i], bl, acc[i][j]);
                            wmma::mma_sync(acc[i][j], al[i], bh, acc[i][j]);
                        }
                    }
                }
            } else {
                wmma::fragment<wmma::matrix_b, 16, 16, 16, ET, wmma::row_major> bh, bl;
                #pragma unroll
                for (int j = 0; j < 4; j++) {
                    wmma::load_matrix_sync(bh, BsH + ks * LDBN + warpN + 16 * j, LDBN);
                    if (!FP16)
                        wmma::load_matrix_sync(bl, BsL + ks * LDBN + warpN + 16 * j, LDBN);
                    #pragma unroll
                    for (int i = 0; i < 2; i++) {
                        wmma::mma_sync(acc[i][j], ah[i], bh, acc[i][j]);
                        if (!FP16) {
                            wmma::mma_sync(acc[i][j], ah[i], bl, acc[i][j]);
                            wmma::mma_sync(acc[i][j], al[i], bh, acc[i][j]);
                        }
                    }
                }
            }
        }
    };

    loadRegs(0);
    splitStore(0);
    __syncthreads();
    for (int kt = 0; kt < nk; kt++) {
        if (kt + 1 < nk) loadRegs(kt + 1);
        compute(kt & 1);
        if (kt + 1 < nk) splitStore((kt + 1) & 1);
        __syncthreads();
    }

    #pragma unroll
    for (int half = 0; half < 2; half++) {
        if (wn == half) {
            #pragma unroll
            for (int i = 0; i < 2; i++)
                #pragma unroll
                for (int j = 0; j < 4; j++)
                    wmma::store_matrix_sync(Cs + (warpM + 16 * i) * LDCs + 16 * j,
                                            acc[i][j], LDCs, wmma::mem_row_major);
        }
        __syncthreads();
        #pragma unroll
        for (int it = 0; it < 8; it++) {
            int idx = it * 256 + tid;
            int row = idx >> 4;
            int c4 = (idx & 15) * 4;
            long gRow;
            if (lists) {
                int pr = prs[row];
                if (pr < 0) continue;
                gRow = pr;
            } else {
                gRow = rowBase + row;
            }
            float4 v = *(float4*)(Cs + row * LDCs + c4);
            int col = colBase + half * 64 + c4;
            v.x *= scale; v.y *= scale; v.z *= scale; v.w *= scale;
            if (bias) {
                v.x += bias[col]; v.y += bias[col + 1];
                v.z += bias[col + 2]; v.w += bias[col + 3];
            }
            if (Res) {
                const float* rp = Res + gRow * ldc + col;
                v.x += rp[0]; v.y += rp[1]; v.z += rp[2]; v.w += rp[3];
            }
            if (relu) {
                v.x = fmaxf(v.x, 0.f); v.y = fmaxf(v.y, 0.f);
                v.z = fmaxf(v.z, 0.f); v.w = fmaxf(v.w, 0.f);
            }
            if constexpr (CH16) {
                __half2 h0 = __floats2half2_rn(v.x, v.y);
                __half2 h1 = __floats2half2_rn(v.z, v.w);
                *(uint2*)(C + gRow * ldc + col) =
                    make_uint2(*(uint32_t*)&h0, *(uint32_t*)&h1);
            } else {
                *(float4*)(C + gRow * ldc + col) = v;
            }
        }
        __syncthreads();
    }
}

// ================= SMALL GEMM: 64x64, BK=32, 128 thr, NN only ==========
template <int FP16, int AH16, int BH16, int CH16>
__global__ __launch_bounds__(128) void wm_gemm_s(
    const void* Av, int lda, long aB, long aHo,
    const void* Bv, int ldb, long bB, long bHo,
    const float* bias, long biasH,
    const float* Res,
    void* Cv, int ldc, long cB, long cHo,
    int N, int K, int nH,
    float scale, int relu,
    const int* __restrict__ lists, int cap,
    const int* __restrict__ counts, int rowShift)
{
    using ET  = typename std::conditional<FP16 != 0, __half, __nv_bfloat16>::type;
    using ATy = typename std::conditional<AH16 != 0, const __half, const float>::type;
    using BTy = typename std::conditional<BH16 != 0, const __half, const float>::type;
    using CTy = typename std::conditional<CH16 != 0, __half, float>::type;
    constexpr int NPL = FP16 ? 1 : 2;
    constexpr int BUFBYTES = NPL * (A_ELs + B_ELs) * 2;

    int z = blockIdx.z, bi = z / nH, hi = z % nH;
    int rowBase = blockIdx.x * BMs;
    int colBase = blockIdx.y * BNs;
    int Me = 0x7fffffff;
    if (lists) {
        Me = counts[hi];
        if (rowBase >= Me) return;
        lists += (long)hi * cap;
    }
    ATy* A  = (ATy*)Av + (long)bi * aB + (long)hi * aHo;
    BTy* Bm = (BTy*)Bv + (long)bi * bB + (long)hi * bHo;
    CTy* C  = (CTy*)Cv + (long)bi * cB + (long)hi * cHo;
    if (Res)  Res  += (long)bi * cB + (long)hi * cHo;
    if (bias) bias += (long)hi * biasH;

    extern __shared__ __align__(16) char dsm[];
    __shared__ int prs[BMs];
    float* Cs = (float*)dsm;

    int tid = threadIdx.x;
    int warp = tid >> 5;
    int wm = warp & 1, wn = warp >> 1;
    int warpM = wm * 32, warpN = wn * 32;

    if (lists) {
        if (tid < BMs) prs[tid] = (rowBase + tid < Me) ? lists[rowBase + tid] : -1;
        __syncthreads();
    }

    int nk = K / BK;
    float4 aP[4], bP[4];

    auto loadRegs = [&](int kt) {
        int k0 = kt * BK;
        #pragma unroll
        for (int p = 0; p < 4; p++) {
            int idx = p * 128 + tid;
            int row = idx >> 3, k4 = (idx & 7) * 4;
            if (lists) {
                int pr = prs[row];
                aP[p] = (pr >= 0) ? ld4(A + (long)(pr >> rowShift) * lda + k0 + k4)
                                  : make_float4(0.f, 0.f, 0.f, 0.f);
            } else {
                aP[p] = ld4(A + (long)(rowBase + row) * lda + k0 + k4);
            }
            int k = idx >> 4, n4 = (idx & 15) * 4;
            bP[p] = ld4(Bm + (long)(k0 + k) * ldb + colBase + n4);
        }
    };

    auto splitStore = [&](int buf) {
        ET* AsH = (ET*)(dsm + buf * BUFBYTES);
        ET* AsL = AsH + A_ELs;
        ET* BsH = AsH + NPL * A_ELs;
        ET* BsL = BsH + B_ELs;
        #pragma unroll
        for (int p = 0; p < 4; p++) {
            int idx = p * 128 + tid;
            int row = idx >> 3, k4 = (idx & 7) * 4;
            uint32_t h0, l0, h1, l1;
            cvt2<FP16>(aP[p].x, aP[p].y, h0, l0);
            cvt2<FP16>(aP[p].z, aP[p].w, h1, l1);
            *(uint32_t*)&AsH[row * LDAs + k4]     = h0;
            *(uint32_t*)&AsH[row * LDAs + k4 + 2] = h1;
            if (!FP16) {
                *(uint32_t*)&AsL[row * LDAs + k4]     = l0;
                *(uint32_t*)&AsL[row * LDAs + k4 + 2] = l1;
            }
            int k = idx >> 4, n4 = (idx & 15) * 4;
            uint32_t bh0, bl0, bh1, bl1;
            cvt2<FP16>(bP[p].x, bP[p].y, bh0, bl0);
            cvt2<FP16>(bP[p].z, bP[p].w, bh1, bl1);
            *(uint32_t*)&BsH[k * LDBNs + n4]     = bh0;
            *(uint32_t*)&BsH[k * LDBNs + n4 + 2] = bh1;
            if (!FP16) {
                *(uint32_t*)&BsL[k * LDBNs + n4]     = bl0;
                *(uint32_t*)&BsL[k * LDBNs + n4 + 2] = bl1;
            }
        }
    };

    wmma::fragment<wmma::accumulator, 16, 16, 16, float> acc[2][2];
    #pragma unroll
    for (int i = 0; i < 2; i++)
        #pragma unroll
        for (int j = 0; j < 2; j++) wmma::fill_fragment(acc[i][j], 0.f);

    auto compute = [&](int buf) {
        ET* AsH = (ET*)(dsm + buf * BUFBYTES);
        ET* AsL = AsH + A_ELs;
        ET* BsH = AsH + NPL * A_ELs;
        ET* BsL = BsH + B_ELs;
        #pragma unroll
        for (int sub = 0; sub < 2; sub++) {
            int ks = sub * 16;
            wmma::fragment<wmma::matrix_a, 16, 16, 16, ET, wmma::row_major> ah[2], al[2];
            #pragma unroll
            for (int i = 0; i < 2; i++) {
                wmma::load_matrix_sync(ah[i], AsH + (warpM + 16 * i) * LDAs + ks, LDAs);
                if (!FP16)
                    wmma::load_matrix_sync(al[i], AsL + (warpM + 16 * i) * LDAs + ks, LDAs);
            }
            wmma::fragment<wmma::matrix_b, 16, 16, 16, ET, wmma::row_major> bh, bl;
            #pragma unroll
            for (int j = 0; j < 2; j++) {
                wmma::load_matrix_sync(bh, BsH + ks * LDBNs + warpN + 16 * j, LDBNs);
                if (!FP16)
                    wmma::load_matrix_sync(bl, BsL + ks * LDBNs + warpN + 16 * j, LDBNs);
                #pragma unroll
                for (int i = 0; i < 2; i++) {
                    wmma::mma_sync(acc[i][j], ah[i], bh, acc[i][j]);
                    if (!FP16) {
                        wmma::mma_sync(acc[i][j], ah[i], bl, acc[i][j]);
                        wmma::mma_sync(acc[i][j], al[i], bh, acc[i][j]);
                    }
                }
            }
        }
    };

    loadRegs(0);
    splitStore(0);
    __syncthreads();
    for (int kt = 0; kt < nk; kt++) {
        if (kt + 1 < nk) loadRegs(kt + 1);
        compute(kt & 1);
        if (kt + 1 < nk) splitStore((kt + 1) & 1);
        __syncthreads();
    }

    #pragma unroll
    for (int i = 0; i < 2; i++)
        #pragma unroll
        for (int j = 0; j < 2; j++)
            wmma::store_matrix_sync(Cs + (warpM + 16 * i) * LDCss + warpN + 16 * j,
                                    acc[i][j], LDCss, wmma::mem_row_major);
    __syncthreads();
    #pragma unroll
    for (int it = 0; it < 8; it++) {
        int idx = it * 128 + tid;
        int row = idx >> 4;
        int c4 = (idx & 15) * 4;
        long gRow;
        if (lists) {
            int pr = prs[row];
            if (pr < 0) continue;
            gRow = pr;
        } else {
            gRow = rowBase + row;
        }
        float4 v = *(float4*)(Cs + row * LDCss + c4);
        int col = colBase + c4;
        v.x *= scale; v.y *= scale; v.z *= scale; v.w *= scale;
        if (bias) {
            v.x += bias[col]; v.y += bias[col + 1];
            v.z += bias[col + 2]; v.w += bias[col + 3];
        }
        if (Res) {
            const float* rp = Res + gRow * ldc + col;
            v.x += rp[0]; v.y += rp[1]; v.z += rp[2]; v.w += rp[3];
        }
        if (relu) {
            v.x = fmaxf(v.x, 0.f); v.y = fmaxf(v.y, 0.f);
            v.z = fmaxf(v.z, 0.f); v.w = fmaxf(v.w, 0.f);
        }
        if constexpr (CH16) {
            __half2 h0 = __floats2half2_rn(v.x, v.y);
            __half2 h1 = __floats2half2_rn(v.z, v.w);
            *(uint2*)(C + gRow * ldc + col) =
                make_uint2(*(uint32_t*)&h0, *(uint32_t*)&h1);
        } else {
            *(float4*)(C + gRow * ldc + col) = v;
        }
    }
}

// ---------------- QKV weight/bias concat ----------------
__global__ void concat_qkv(const float* __restrict__ wq, const float* __restrict__ wk,
                           const float* __restrict__ wv, const float* __restrict__ bq,
                           const float* __restrict__ bk, const float* __restrict__ bv)
{
    int i = blockIdx.x * blockDim.x + threadIdx.x;   // D*D/4 per weight
    if (i < D * D / 4) {
        int row = i / (D / 4), c4 = (i % (D / 4)) * 4;
        float4* dst = (float4*)(g_wqkv + (long)row * D3);
        dst[c4 / 4]             = *(const float4*)(wq + (long)row * D + c4);
        dst[(D + c4) / 4]       = *(const float4*)(wk + (long)row * D + c4);
        dst[(2 * D + c4) / 4]   = *(const float4*)(wv + (long)row * D + c4);
    }
    if (i < D) {
        g_bqkv[i] = bq[i];
        g_bqkv[D + i] = bk[i];
        g_bqkv[2 * D + i] = bv[i];
    }
}

// ---------------- gate + softmax + top-2 + scatter ----------------
template <int KD>
__global__ void gate_topk(
    const float* __restrict__ X, const float* __restrict__ GW,
    const float* __restrict__ GB, float* __restrict__ tw,
    int* __restrict__ lists, int* __restrict__ counts, int cap, int T)
{
    int warp = (blockIdx.x * blockDim.x + threadIdx.x) >> 5;
    int lane = threadIdx.x & 31;
    if (warp >= T) return;
    const float* x = X + (long)warp * KD;
    float xv[KD / 32];
#pragma unroll
    for (int i = 0; i < KD / 32; i++) xv[i] = x[lane + 32 * i];
    float p[E] = {0.f, 0.f, 0.f, 0.f, 0.f, 0.f, 0.f, 0.f};
#pragma unroll
    for (int i = 0; i < KD / 32; i++) {
        float xvi = xv[i];
        const float4* g = (const float4*)(GW + (long)(lane + 32 * i) * E);
        float4 a = g[0], b4 = g[1];
        p[0] += xvi * a.x;  p[1] += xvi * a.y;
        p[2] += xvi * a.z;  p[3] += xvi * a.w;
        p[4] += xvi * b4.x; p[5] += xvi * b4.y;
        p[6] += xvi * b4.z; p[7] += xvi * b4.w;
    }
#pragma unroll
    for (int e = 0; e < E; e++) {
#pragma unroll
        for (int o = 16; o > 0; o >>= 1) p[e] += __shfl_xor_sync(0xffffffffu, p[e], o);
        p[e] += GB[e];
    }
    float m = p[0];
#pragma unroll
    for (int e = 1; e < E; e++) m = fmaxf(m, p[e]);
    float sum = 0.f;
#pragma unroll
    for (int e = 0; e < E; e++) { p[e] = expf(p[e] - m); sum += p[e]; }
    float inv = 1.f / sum;
#pragma unroll
    for (int e = 0; e < E; e++) p[e] *= inv;
    float v0 = -1e30f; int i0 = 0;
#pragma unroll
    for (int e = 0; e < E; e++) if (p[e] > v0) { v0 = p[e]; i0 = e; }
    float v1 = -1e30f; int i1 = 0;
#pragma unroll
    for (int e = 0; e < E; e++) if (e != i0 && p[e] > v1) { v1 = p[e]; i1 = e; }
    float e0 = expf(v0), e1 = expf(v1);
    float wi = 1.f / (e0 + e1);
    if (lane == 0) {
        tw[warp * 2 + 0] = e0 * wi;
        tw[warp * 2 + 1] = e1 * wi;
        int pos0 = atomicAdd(&counts[i0], 1);
        lists[i0 * cap + pos0] = warp * 2;
        int pos1 = atomicAdd(&counts[i1], 1);
        lists[i1 * cap + pos1] = warp * 2 + 1;
    }
}

// ---------------- layernorm (D=512, block=256) ----------------
__global__ void layernorm_k(const float* __restrict__ X,
                            const float* __restrict__ w,
                            const float* __restrict__ b,
                            float* __restrict__ Y)
{
    int row = blockIdx.x;
    const float* x = X + (long)row * D;
    float* y = Y + (long)row * D;
    int tid = threadIdx.x;
    float x0 = x[tid], x1 = x[tid + 256];
    __shared__ float red[256];
    red[tid] = x0 + x1;
    __syncthreads();
    for (int o = 128; o > 0; o >>= 1) { if (tid < o) red[tid] += red[tid + o]; __syncthreads(); }
    float mu = red[0] * (1.f / D);
    __syncthreads();
    float d0 = x0 - mu, d1 = x1 - mu;
    red[tid] = d0 * d0 + d1 * d1;
    __syncthreads();
    for (int o = 128; o > 0; o >>= 1) { if (tid < o) red[tid] += red[tid + o]; __syncthreads(); }
    float rs = rsqrtf(red[0] * (1.f / D) + 1e-12f);
    y[tid]       = d0 * rs * w[tid]       + b[tid];
    y[tid + 256] = d1 * rs * w[tid + 256] + b[tid + 256];
}

// ---------------- row softmax on half scores ----------------
__global__ void softmax_rows_h(__half* __restrict__ Sm)
{
    __half* s = Sm + (long)blockIdx.x * S;
    int tid = threadIdx.x;
    float v[4];
#pragma unroll
    for (int i = 0; i < 4; i++) v[i] = __half2float(s[tid + 256 * i]);
    __shared__ float red[256];
    float m = fmaxf(fmaxf(v[0], v[1]), fmaxf(v[2], v[3]));
    red[tid] = m;
    __syncthreads();
    for (int o = 128; o > 0; o >>= 1) { if (tid < o) red[tid] = fmaxf(red[tid], red[tid + o]); __syncthreads(); }
    m = red[0];
    __syncthreads();
    float t = 0.f;
#pragma unroll
    for (int i = 0; i < 4; i++) { v[i] = expf(v[i] - m); t += v[i]; }
    red[tid] = t;
    __syncthreads();
    for (int o = 128; o > 0; o >>= 1) { if (tid < o) red[tid] += red[tid + o]; __syncthreads(); }
    float inv = 1.f / red[0];
#pragma unroll
    for (int i = 0; i < 4; i++) s[tid + 256 * i] = __float2half(v[i] * inv);
}

// ---------------- small elementwise kernels ----------------
__global__ void zero_counts() { if (threadIdx.x < E) g_counts[threadIdx.x] = 0; }

__global__ void copy_xf()
{
    int idx = blockIdx.x * blockDim.x + threadIdx.x;
    int t = idx >> 7, c = idx & 127;
    int bb = t >> 12, h = (t >> 10) & 3, s = t & 1023;
    g_xf[idx] = g_xp[((long)(bb * S + s)) * D + h * HD + c];
}

__global__ void combine_local()
{
    int idx = blockIdx.x * blockDim.x + threadIdx.x;
    int t = idx >> 7, c = idx & 127;
    float v = g_xf[idx]
            + g_tw[2 * t]     * g_po[(long)(2 * t) * HD + c]
            + g_tw[2 * t + 1] * g_po[(long)(2 * t + 1) * HD + c];
    int bb = t >> 12, h = (t >> 10) & 3, s = t & 1023;
    g_buf1[((long)(bb * S + s)) * D + h * HD + c] = v;
}

__global__ void final_combine(float* __restrict__ out)
{
    int idx = blockIdx.x * blockDim.x + threadIdx.x;
    int t = idx >> 9, c = idx & 511;
    out[idx] = g_x1[idx]
             + g_tw[2 * t]     * g_po[(long)(2 * t) * D + c]
             + g_tw[2 * t + 1] * g_po[(long)(2 * t + 1) * D + c];
}

// ---------------- launch ----------------
extern "C" void kernel_launch(void* const* d_in, const int* in_sizes, int n_in,
                              void* d_out, int out_size)
{
    const float* x       = (const float*)d_in[0];
    const float* pre_w   = (const float*)d_in[1];
    const float* pre_b   = (const float*)d_in[2];
    const float* l_gw    = (const float*)d_in[3];
    const float* l_gb    = (const float*)d_in[4];
    const float* l_w1    = (const float*)d_in[5];
    const float* l_b1    = (const float*)d_in[6];
    const float* l_w2    = (const float*)d_in[7];
    const float* l_b2    = (const float*)d_in[8];
    const float* align_w = (const float*)d_in[9];
    const float* align_b = (const float*)d_in[10];
    const float* ln1_w   = (const float*)d_in[11];
    const float* ln1_b   = (const float*)d_in[12];
    const float* wq      = (const float*)d_in[13];
    const float* bq      = (const float*)d_in[14];
    const float* wk      = (const float*)d_in[15];
    const float* bk      = (const float*)d_in[16];
    const float* wv      = (const float*)d_in[17];
    const float* bv      = (const float*)d_in[18];
    const float* wo      = (const float*)d_in[19];
    const float* bo      = (const float*)d_in[20];
    const float* ln2_w   = (const float*)d_in[21];
    const float* ln2_b   = (const float*)d_in[22];
    const float* g_gw    = (const float*)d_in[23];
    const float* g_gb    = (const float*)d_in[24];
    const float* gw1     = (const float*)d_in[25];
    const float* gb1     = (const float*)d_in[26];
    const float* gw2     = (const float*)d_in[27];
    const float* gb2     = (const float*)d_in[28];
    float* out = (float*)d_out;

    float *xp, *xf, *po, *buf1, *xl, *xn, *QKV, *O, *x1, *x2, *tw, *wqkv, *bqkv;
    __half *H, *Sch;
    int *lists, *counts;
    cudaGetSymbolAddress((void**)&xp, g_xp);
    cudaGetSymbolAddress((void**)&xf, g_xf);
    cudaGetSymbolAddress((void**)&H, g_H);
    cudaGetSymbolAddress((void**)&po, g_po);
    cudaGetSymbolAddress((void**)&buf1, g_buf1);
    cudaGetSymbolAddress((void**)&xl, g_xl);
    cudaGetSymbolAddress((void**)&xn, g_xn);
    cudaGetSymbolAddress((void**)&QKV, g_QKV);
    cudaGetSymbolAddress((void**)&Sch, g_Sch);
    cudaGetSymbolAddress((void**)&O, g_O);
    cudaGetSymbolAddress((void**)&x1, g_x1);
    cudaGetSymbolAddress((void**)&x2, g_x2);
    cudaGetSymbolAddress((void**)&tw, g_tw);
    cudaGetSymbolAddress((void**)&lists, g_lists);
    cudaGetSymbolAddress((void**)&counts, g_counts);
    cudaGetSymbolAddress((void**)&wqkv, g_wqkv);
    cudaGetSymbolAddress((void**)&bqkv, g_bqkv);

    cudaFuncSetAttribute(wm_gemm<1,1,0,0,1>, cudaFuncAttributeMaxDynamicSharedMemorySize, SMEM_BIG_NT_F16);
    cudaFuncSetAttribute(wm_gemm<0,1,0,0,1>, cudaFuncAttributeMaxDynamicSharedMemorySize, SMEM_BIG_NN_F16);
    cudaFuncSetAttribute(wm_gemm_s<0,0,0,0>, cudaFuncAttributeMaxDynamicSharedMemorySize, SMEM_S_SPLIT);
    cudaFuncSetAttribute(wm_gemm_s<1,0,0,0>, cudaFuncAttributeMaxDynamicSharedMemorySize, SMEM_S_F16);
    cudaFuncSetAttribute(wm_gemm_s<1,1,0,0>, cudaFuncAttributeMaxDynamicSharedMemorySize, SMEM_S_F16);

    const float rscale = 0.08838834764831845f;  // 1/sqrt(128)

    // 0. concat QKV weights + biases (cheap; overlaps nothing critical)
    concat_qkv<<<(D * D / 4 + 255) / 256, 256>>>(wq, wk, wv, bq, bk, bv);

    // 1. xp = x @ pre_w + pre_b  (split-bf16: feeds local gate top-2)
    wm_gemm_s<0,0,0,0><<<dim3(TOK / BMs, D / BNs, 1), 128, SMEM_S_SPLIT>>>(
        x, D, 0, 0, pre_w, D, 0, 0, pre_b, 0, nullptr,
        xp, D, 0, 0, D, D, 1, 1.f, 0, nullptr, 0, nullptr, 0);

    // 2. reshape to local sub-tokens
    copy_xf<<<LTOK * HD / 256, 256>>>();

    // 3-4. local gate + top2
    zero_counts<<<1, 32>>>();
    gate_topk<HD><<<LTOK / 4, 128>>>(xf, l_gw, l_gb, tw, lists, counts, CAP, LTOK);

    // 5. H = relu(xf @ l_w1 + b1)  (fp16 compute, C half, big)
    wm_gemm<0,1,0,0,1><<<dim3(LPAIRS / BM, HID / BN, E), 256, SMEM_BIG_NN_F16>>>(
        xf, HD, 0, 0, l_w1, HID, 0, (long)HD * HID, l_b1, HID, nullptr,
        H, HID, 0, 0, HID, HD, E, 1.f, 1, lists, CAP, counts, 1);

    // 6. po = H @ l_w2 + b2  (small: 512 CTAs; A half)
    wm_gemm_s<1,1,0,0><<<dim3(LPAIRS / BMs, HD / BNs, E), 128, SMEM_S_F16>>>(
        H, HID, 0, 0, l_w2, HD, 0, (long)HID * HD, l_b2, HD, nullptr,
        po, HD, 0, 0, HD, HID, E, 1.f, 0, lists, CAP, counts, 0);

    // 7. xf + weighted expert out -> [b,s,d]
    combine_local<<<LTOK * HD / 256, 256>>>();

    // 8. align projection (fp16)
    wm_gemm_s<1,0,0,0><<<dim3(TOK / BMs, D / BNs, 1), 128, SMEM_S_F16>>>(
        buf1, D, 0, 0, align_w, D, 0, 0, align_b, 0, nullptr,
        xl, D, 0, 0, D, D, 1, 1.f, 0, nullptr, 0, nullptr, 0);

    // 9. ln1
    layernorm_k<<<TOK, 256>>>(xl, ln1_w, ln1_b, xn);

    // 10. fused QKV projection (768 CTAs)
    wm_gemm_s<1,0,0,0><<<dim3(TOK / BMs, D3 / BNs, 1), 128, SMEM_S_F16>>>(
        xn, D, 0, 0, wqkv, D3, 0, 0, bqkv, 0, nullptr,
        QKV, D3, 0, 0, D3, D, 1, 1.f, 0, nullptr, 0, nullptr, 0);

    // 13. scores = Q @ K^T / sqrt(DK)  (NT fp16, C half)
    wm_gemm<1,1,0,0,1><<<dim3(S / BM, S / BN, Bsz * AH), 256, SMEM_BIG_NT_F16>>>(
        QKV, D3, (long)S * D3, DK, QKV + D, D3, (long)S * D3, DK, nullptr, 0, nullptr,
        Sch, S, (long)AH * S * S, (long)S * S,
        S, DK, AH, rscale, 0, nullptr, 0, nullptr, 0);

    // 14. softmax rows (half)
    softmax_rows_h<<<Bsz * AH * S, 256>>>(Sch);

    // 15. O = P @ V  (A half)
    wm_gemm_s<1,1,0,0><<<dim3(S / BMs, DK / BNs, Bsz * AH), 128, SMEM_S_F16>>>(
        Sch, S, (long)AH * S * S, (long)S * S,
        QKV + 2 * D, D3, (long)S * D3, DK, nullptr, 0, nullptr,
        O, D, (long)S * D, DK, DK, S, AH, 1.f, 0, nullptr, 0, nullptr, 0);

    // 16. x1 = x + O @ wo + bo  (fp16)
    wm_gemm_s<1,0,0,0><<<dim3(TOK / BMs, D / BNs, 1), 128, SMEM_S_F16>>>(
        O, D, 0, 0, wo, D, 0, 0, bo, 0, x,
        x1, D, 0, 0, D, D, 1, 1.f, 0, nullptr, 0, nullptr, 0);

    // 17. ln2
    layernorm_k<<<TOK, 256>>>(x1, ln2_w, ln2_b, x2);

    // 18-19. global gate + top2
    zero_counts<<<1, 32>>>();
    gate_topk<D><<<TOK / 4, 128>>>(x2, g_gw, g_gb, tw, lists, counts, CAP, TOK);

    // 20. H = relu(x2 @ gw1 + b1)  (fp16 compute, C half, big)
    wm_gemm<0,1,0,0,1><<<dim3(GPAIRS / BM, HID / BN, E), 256, SMEM_BIG_NN_F16>>>(
        x2, D, 0, 0, gw1, HID, 0, (long)D * HID, gb1, HID, nullptr,
        H, HID, 0, 0, HID, D, E, 1.f, 1, lists, CAP, counts, 1);

    // 21. po = H @ gw2 + b2  (small: ~512 CTAs; A half)
    wm_gemm_s<1,1,0,0><<<dim3(GPAIRS / BMs, D / BNs, E), 128, SMEM_S_F16>>>(
        H, HID, 0, 0, gw2, D, 0, (long)HID * D, gb2, D, nullptr,
        po, D, 0, 0, D, HID, E, 1.f, 0, lists, CAP, counts, 0);

    // 22. out = x1 + weighted expert out
    final_combine<<<TOK * D / 256, 256>>>(out);
}

// round 15
// speedup vs baseline: 1.1594x; 1.0110x over previous
#include <cuda_runtime.h>
#include <cuda_bf16.h>
#include <cuda_fp16.h>
#include <mma.h>
#include <math.h>
#include <stdint.h>
#include <type_traits>

using namespace nvcuda;

// ---------------- problem constants ----------------
constexpr int Bsz = 2, S = 1024, D = 512;
constexpr int E = 8;
constexpr int HMOE = 4, HD = 128, HID = 2048;
constexpr int AH = 4, DK = 128;
constexpr int TOK = Bsz * S;              // 2048
constexpr int LTOK = TOK * HMOE;          // 8192
constexpr int LPAIRS = LTOK * 2;          // 16384
constexpr int GPAIRS = TOK * 2;           // 4096
constexpr int CAP = LPAIRS;
constexpr int D3 = 3 * D;                 // 1536 (QKV fused)

// ---------------- scratch (device globals) ------
__device__ float  g_xp[TOK * D];
__device__ float  g_xf[LTOK * HD];
__device__ __half g_H[LPAIRS * HID];           // half
__device__ float  g_po[LPAIRS * HD];
__device__ float  g_buf1[TOK * D];
__device__ float  g_xl[TOK * D];
__device__ float  g_xn[TOK * D];
__device__ float  g_QKV[TOK * D3];             // packed Q|K|V
__device__ __half g_Sch[Bsz * AH * S * S];     // half scores
__device__ float  g_O[TOK * D];
__device__ float  g_x1[TOK * D];
__device__ float  g_x2[TOK * D];
__device__ float  g_tw[LPAIRS];
__device__ int    g_lists[E * CAP];
__device__ int    g_counts[2 * E];             // [0]=local gate, [E]=global gate
__device__ float  g_wqkv[D * D3];
__device__ float  g_bqkv[D3];

// ================= conversion helpers =================
__device__ __forceinline__ void split2p(float a, float b, uint32_t& hi, uint32_t& lo)
{
    __nv_bfloat162 h = __floats2bfloat162_rn(a, b);
    float ra = a - __bfloat162float(h.x);
    float rb = b - __bfloat162float(h.y);
    __nv_bfloat162 l = __floats2bfloat162_rn(ra, rb);
    hi = *(uint32_t*)&h;
    lo = *(uint32_t*)&l;
}
template <int FP16>
__device__ __forceinline__ void cvt2(float a, float b, uint32_t& hi, uint32_t& lo)
{
    if constexpr (FP16) {
        __half2 h = __floats2half2_rn(a, b);
        hi = *(uint32_t*)&h;
        lo = 0;
    } else {
        split2p(a, b, hi, lo);
    }
}
__device__ __forceinline__ float4 ld4(const float* p) { return *(const float4*)p; }
__device__ __forceinline__ float4 ld4(const __half* p)
{
    uint2 r = *(const uint2*)p;
    __half2 h0 = *(__half2*)&r.x, h1 = *(__half2*)&r.y;
    float2 f0 = __half22float2(h0), f1 = __half22float2(h1);
    return make_float4(f0.x, f0.y, f1.x, f1.y);
}

// ================= tile geometry =================
constexpr int BM = 128, BN = 128, BK = 32;
constexpr int LDA  = BK + 8;    // 40
constexpr int LDBT = BK + 8;    // 40
constexpr int LDBN = BN + 8;    // 136
constexpr int LDCs = 64 + 8;    // 72
constexpr int A_ELEMS   = BM * LDA;
constexpr int BT_ELEMS  = BN * LDBT;
constexpr int BNN_ELEMS = BK * LDBN;

constexpr int BMs = 64, BNs = 64;
constexpr int LDAs  = BK + 8;
constexpr int LDBNs = BNs + 8;
constexpr int LDCss = BNs + 8;
constexpr int A_ELs = BMs * LDAs;
constexpr int B_ELs = BK * LDBNs;

constexpr int SMEM_BIG_NT_F16 = 2 * 1 * (A_ELEMS + BT_ELEMS) * 2;
constexpr int SMEM_BIG_NN_F16 = 2 * 1 * (A_ELEMS + BNN_ELEMS) * 2;
constexpr int SMEM_S_SPLIT    = 2 * 2 * (A_ELs + B_ELs) * 2;
constexpr int SMEM_S_F16      = 2 * 1 * (A_ELs + B_ELs) * 2;

// ================= BIG GEMM: 128x128, BK=32, 256 thr =================
template <int TRANSB, int FP16, int AH16, int BH16, int CH16>
__global__ __launch_bounds__(256) void wm_gemm(
    const void* Av, int lda, long aB, long aHo,
    const void* Bv, int ldb, long bB, long bHo,
    const float* bias, long biasH,
    const float* Res,
    void* Cv, int ldc, long cB, long cHo,
    int N, int K, int nH,
    float scale, int relu,
    const int* __restrict__ lists, int cap,
    const int* __restrict__ counts, int rowShift)
{
    using ET  = typename std::conditional<FP16 != 0, __half, __nv_bfloat16>::type;
    using ATy = typename std::conditional<AH16 != 0, const __half, const float>::type;
    using BTy = typename std::conditional<BH16 != 0, const __half, const float>::type;
    using CTy = typename std::conditional<CH16 != 0, __half, float>::type;
    constexpr int NPL = FP16 ? 1 : 2;
    constexpr int B_ELEMS  = TRANSB ? BT_ELEMS : BNN_ELEMS;
    constexpr int BUFBYTES = NPL * (A_ELEMS + B_ELEMS) * 2;

    int z = blockIdx.z, bi = z / nH, hi = z % nH;
    int rowBase = blockIdx.x * BM;
    int colBase = blockIdx.y * BN;
    int Me = 0x7fffffff;
    if (lists) {
        Me = counts[hi];
        if (rowBase >= Me) return;
        lists += (long)hi * cap;
    }
    ATy* A  = (ATy*)Av + (long)bi * aB + (long)hi * aHo;
    BTy* Bm = (BTy*)Bv + (long)bi * bB + (long)hi * bHo;
    CTy* C  = (CTy*)Cv + (long)bi * cB + (long)hi * cHo;
    if (Res)  Res  += (long)bi * cB + (long)hi * cHo;
    if (bias) bias += (long)hi * biasH;

    extern __shared__ __align__(16) char dsm[];
    __shared__ int prs[BM];
    float* Cs = (float*)dsm;

    int tid = threadIdx.x;
    int warp = tid >> 5;
    int wm = warp & 3, wn = warp >> 2;
    int warpM = wm * 32, warpN = wn * 64;

    if (lists) {
        if (tid < BM) prs[tid] = (rowBase + tid < Me) ? lists[rowBase + tid] : -1;
        __syncthreads();
    }

    int nk = K / BK;
    float4 aP[4], bP[4];

    auto loadRegs = [&](int kt) {
        int k0 = kt * BK;
        #pragma unroll
        for (int p = 0; p < 4; p++) {
            int idx = p * 256 + tid;
            int row = idx >> 3, k4 = (idx & 7) * 4;
            if (lists) {
                int pr = prs[row];
                aP[p] = (pr >= 0) ? ld4(A + (long)(pr >> rowShift) * lda + k0 + k4)
                                  : make_float4(0.f, 0.f, 0.f, 0.f);
            } else {
                aP[p] = ld4(A + (long)(rowBase + row) * lda + k0 + k4);
            }
            if (TRANSB) {
                int n = idx >> 3, bk4 = (idx & 7) * 4;
                bP[p] = ld4(Bm + (long)(colBase + n) * ldb + k0 + bk4);
            } else {
                int k = idx >> 5, n4 = (idx & 31) * 4;
                bP[p] = ld4(Bm + (long)(k0 + k) * ldb + colBase + n4);
            }
        }
    };

    auto splitStore = [&](int buf) {
        ET* AsH = (ET*)(dsm + buf * BUFBYTES);
        ET* AsL = AsH + A_ELEMS;
        ET* BsH = AsH + NPL * A_ELEMS;
        ET* BsL = BsH + B_ELEMS;
        #pragma unroll
        for (int p = 0; p < 4; p++) {
            int idx = p * 256 + tid;
            int row = idx >> 3, k4 = (idx & 7) * 4;
            uint32_t h0, l0, h1, l1;
            cvt2<FP16>(aP[p].x, aP[p].y, h0, l0);
            cvt2<FP16>(aP[p].z, aP[p].w, h1, l1);
            *(uint32_t*)&AsH[row * LDA + k4]     = h0;
            *(uint32_t*)&AsH[row * LDA + k4 + 2] = h1;
            if (!FP16) {
                *(uint32_t*)&AsL[row * LDA + k4]     = l0;
                *(uint32_t*)&AsL[row * LDA + k4 + 2] = l1;
            }
            if (TRANSB) {
                int n = idx >> 3, bk4 = (idx & 7) * 4;
                uint32_t bh0, bl0, bh1, bl1;
                cvt2<FP16>(bP[p].x, bP[p].y, bh0, bl0);
                cvt2<FP16>(bP[p].z, bP[p].w, bh1, bl1);
                *(uint32_t*)&BsH[n * LDBT + bk4]     = bh0;
                *(uint32_t*)&BsH[n * LDBT + bk4 + 2] = bh1;
                if (!FP16) {
                    *(uint32_t*)&BsL[n * LDBT + bk4]     = bl0;
                    *(uint32_t*)&BsL[n * LDBT + bk4 + 2] = bl1;
                }
            } else {
                int k = idx >> 5, n4 = (idx & 31) * 4;
                uint32_t bh0, bl0, bh1, bl1;
                cvt2<FP16>(bP[p].x, bP[p].y, bh0, bl0);
                cvt2<FP16>(bP[p].z, bP[p].w, bh1, bl1);
                *(uint32_t*)&BsH[k * LDBN + n4]     = bh0;
                *(uint32_t*)&BsH[k * LDBN + n4 + 2] = bh1;
                if (!FP16) {
                    *(uint32_t*)&BsL[k * LDBN + n4]     = bl0;
                    *(uint32_t*)&BsL[k * LDBN + n4 + 2] = bl1;
                }
            }
        }
    };

    wmma::fragment<wmma::accumulator, 16, 16, 16, float> acc[2][4];
    #pragma unroll
    for (int i = 0; i < 2; i++)
        #pragma unroll
        for (int j = 0; j < 4; j++) wmma::fill_fragment(acc[i][j], 0.f);

    auto compute = [&](int buf) {
        ET* AsH = (ET*)(dsm + buf * BUFBYTES);
        ET* AsL = AsH + A_ELEMS;
        ET* BsH = AsH + NPL * A_ELEMS;
        ET* BsL = BsH + B_ELEMS;
        #pragma unroll
        for (int sub = 0; sub < 2; sub++) {
            int ks = sub * 16;
            wmma::fragment<wmma::matrix_a, 16, 16, 16, ET, wmma::row_major> ah[2], al[2];
            #pragma unroll
            for (int i = 0; i < 2; i++) {
                wmma::load_matrix_sync(ah[i], AsH + (warpM + 16 * i) * LDA + ks, LDA);
                if (!FP16)
                    wmma::load_matrix_sync(al[i], AsL + (warpM + 16 * i) * LDA + ks, LDA);
            }
            if (TRANSB) {
                wmma::fragment<wmma::matrix_b, 16, 16, 16, ET, wmma::col_major> bh, bl;
                #pragma unroll
                for (int j = 0; j < 4; j++) {
                    wmma::load_matrix_sync(bh, BsH + (warpN + 16 * j) * LDBT + ks, LDBT);
                    if (!FP16)
                        wmma::load_matrix_sync(bl, BsL + (warpN + 16 * j) * LDBT + ks, LDBT);
                    #pragma unroll
                    for (int i = 0; i < 2; i++) {
                        wmma::mma_sync(acc[i][j], ah[i], bh, acc[i][j]);
                        if (!FP16) {
                            wmma::mma_sync(acc[i][j], ah[i], bl, acc[i][j]);
                            wmma::mma_sync(acc[i][j], al[i], bh, acc[i][j]);
                        }
                    }
                }
            } else {
                wmma::fragment<wmma::matrix_b, 16, 16, 16, ET, wmma::row_major> bh, bl;
                #pragma unroll
                for (int j = 0; j < 4; j++) {
                    wmma::load_matrix_sync(bh, BsH + ks * LDBN + warpN + 16 * j, LDBN);
                    if (!FP16)
                        wmma::load_matrix_sync(bl, BsL + ks * LDBN + warpN + 16 * j, LDBN);
                    #pragma unroll
                    for (int i = 0; i < 2; i++) {
                        wmma::mma_sync(acc[i][j], ah[i], bh, acc[i][j]);
                        if (!FP16) {
                            wmma::mma_sync(acc[i][j], ah[i], bl, acc[i][j]);
                            wmma::mma_sync(acc[i][j], al[i], bh, acc[i][j]);
                        }
                    }
                }
            }
        }
    };

    loadRegs(0);
    splitStore(0);
    __syncthreads();
    for (int kt = 0; kt < nk; kt++) {
        if (kt + 1 < nk) loadRegs(kt + 1);
        compute(kt & 1);
        if (kt + 1 < nk) splitStore((kt + 1) & 1);
        __syncthreads();
    }

    #pragma unroll
    for (int half = 0; half < 2; half++) {
        if (wn == half) {
            #pragma unroll
            for (int i = 0; i < 2; i++)
                #pragma unroll
                for (int j = 0; j < 4; j++)
                    wmma::store_matrix_sync(Cs + (warpM + 16 * i) * LDCs + 16 * j,
                                            acc[i][j], LDCs, wmma::mem_row_major);
        }
        __syncthreads();
        #pragma unroll
        for (int it = 0; it < 8; it++) {
            int idx = it * 256 + tid;
            int row = idx >> 4;
            int c4 = (idx & 15) * 4;
            long gRow;
            if (lists) {
                int pr = prs[row];
                if (pr < 0) continue;
                gRow = pr;
            } else {
                gRow = rowBase + row;
            }
            float4 v = *(float4*)(Cs + row * LDCs + c4);
            int col = colBase + half * 64 + c4;
            v.x *= scale; v.y *= scale; v.z *= scale; v.w *= scale;
            if (bias) {
                v.x += bias[col]; v.y += bias[col + 1];
                v.z += bias[col + 2]; v.w += bias[col + 3];
            }
            if (Res) {
                const float* rp = Res + gRow * ldc + col;
                v.x += rp[0]; v.y += rp[1]; v.z += rp[2]; v.w += rp[3];
            }
            if (relu) {
                v.x = fmaxf(v.x, 0.f); v.y = fmaxf(v.y, 0.f);
                v.z = fmaxf(v.z, 0.f); v.w = fmaxf(v.w, 0.f);
            }
            if constexpr (CH16) {
                __half2 h0 = __floats2half2_rn(v.x, v.y);
                __half2 h1 = __floats2half2_rn(v.z, v.w);
                *(uint2*)(C + gRow * ldc + col) =
                    make_uint2(*(uint32_t*)&h0, *(uint32_t*)&h1);
            } else {
                *(float4*)(C + gRow * ldc + col) = v;
            }
        }
        __syncthreads();
    }
}

// ================= SMALL GEMM: 64x64, BK=32, 128 thr, NN only ==========
// XFW: also scatter C into g_xf local-sub-token layout (used by xp GEMM).
template <int FP16, int AH16, int BH16, int CH16, int XFW>
__global__ __launch_bounds__(128) void wm_gemm_s(
    const void* Av, int lda, long aB, long aHo,
    const void* Bv, int ldb, long bB, long bHo,
    const float* bias, long biasH,
    const float* Res,
    void* Cv, int ldc, long cB, long cHo,
    int N, int K, int nH,
    float scale, int relu,
    const int* __restrict__ lists, int cap,
    const int* __restrict__ counts, int rowShift)
{
    using ET  = typename std::conditional<FP16 != 0, __half, __nv_bfloat16>::type;
    using ATy = typename std::conditional<AH16 != 0, const __half, const float>::type;
    using BTy = typename std::conditional<BH16 != 0, const __half, const float>::type;
    using CTy = typename std::conditional<CH16 != 0, __half, float>::type;
    constexpr int NPL = FP16 ? 1 : 2;
    constexpr int BUFBYTES = NPL * (A_ELs + B_ELs) * 2;

    int z = blockIdx.z, bi = z / nH, hi = z % nH;
    int rowBase = blockIdx.x * BMs;
    int colBase = blockIdx.y * BNs;
    int Me = 0x7fffffff;
    if (lists) {
        Me = counts[hi];
        if (rowBase >= Me) return;
        lists += (long)hi * cap;
    }
    ATy* A  = (ATy*)Av + (long)bi * aB + (long)hi * aHo;
    BTy* Bm = (BTy*)Bv + (long)bi * bB + (long)hi * bHo;
    CTy* C  = (CTy*)Cv + (long)bi * cB + (long)hi * cHo;
    if (Res)  Res  += (long)bi * cB + (long)hi * cHo;
    if (bias) bias += (long)hi * biasH;

    extern __shared__ __align__(16) char dsm[];
    __shared__ int prs[BMs];
    float* Cs = (float*)dsm;

    int tid = threadIdx.x;
    int warp = tid >> 5;
    int wm = warp & 1, wn = warp >> 1;
    int warpM = wm * 32, warpN = wn * 32;

    if (lists) {
        if (tid < BMs) prs[tid] = (rowBase + tid < Me) ? lists[rowBase + tid] : -1;
        __syncthreads();
    }

    int nk = K / BK;
    float4 aP[4], bP[4];

    auto loadRegs = [&](int kt) {
        int k0 = kt * BK;
        #pragma unroll
        for (int p = 0; p < 4; p++) {
            int idx = p * 128 + tid;
            int row = idx >> 3, k4 = (idx & 7) * 4;
            if (lists) {
                int pr = prs[row];
                aP[p] = (pr >= 0) ? ld4(A + (long)(pr >> rowShift) * lda + k0 + k4)
                                  : make_float4(0.f, 0.f, 0.f, 0.f);
            } else {
                aP[p] = ld4(A + (long)(rowBase + row) * lda + k0 + k4);
            }
            int k = idx >> 4, n4 = (idx & 15) * 4;
            bP[p] = ld4(Bm + (long)(k0 + k) * ldb + colBase + n4);
        }
    };

    auto splitStore = [&](int buf) {
        ET* AsH = (ET*)(dsm + buf * BUFBYTES);
        ET* AsL = AsH + A_ELs;
        ET* BsH = AsH + NPL * A_ELs;
        ET* BsL = BsH + B_ELs;
        #pragma unroll
        for (int p = 0; p < 4; p++) {
            int idx = p * 128 + tid;
            int row = idx >> 3, k4 = (idx & 7) * 4;
            uint32_t h0, l0, h1, l1;
            cvt2<FP16>(aP[p].x, aP[p].y, h0, l0);
            cvt2<FP16>(aP[p].z, aP[p].w, h1, l1);
            *(uint32_t*)&AsH[row * LDAs + k4]     = h0;
            *(uint32_t*)&AsH[row * LDAs + k4 + 2] = h1;
            if (!FP16) {
                *(uint32_t*)&AsL[row * LDAs + k4]     = l0;
                *(uint32_t*)&AsL[row * LDAs + k4 + 2] = l1;
            }
            int k = idx >> 4, n4 = (idx & 15) * 4;
            uint32_t bh0, bl0, bh1, bl1;
            cvt2<FP16>(bP[p].x, bP[p].y, bh0, bl0);
            cvt2<FP16>(bP[p].z, bP[p].w, bh1, bl1);
            *(uint32_t*)&BsH[k * LDBNs + n4]     = bh0;
            *(uint32_t*)&BsH[k * LDBNs + n4 + 2] = bh1;
            if (!FP16) {
                *(uint32_t*)&BsL[k * LDBNs + n4]     = bl0;
                *(uint32_t*)&BsL[k * LDBNs + n4 + 2] = bl1;
            }
        }
    };

    wmma::fragment<wmma::accumulator, 16, 16, 16, float> acc[2][2];
    #pragma unroll
    for (int i = 0; i < 2; i++)
        #pragma unroll
        for (int j = 0; j < 2; j++) wmma::fill_fragment(acc[i][j], 0.f);

    auto compute = [&](int buf) {
        ET* AsH = (ET*)(dsm + buf * BUFBYTES);
        ET* AsL = AsH + A_ELs;
        ET* BsH = AsH + NPL * A_ELs;
        ET* BsL = BsH + B_ELs;
        #pragma unroll
        for (int sub = 0; sub < 2; sub++) {
            int ks = sub * 16;
            wmma::fragment<wmma::matrix_a, 16, 16, 16, ET, wmma::row_major> ah[2], al[2];
            #pragma unroll
            for (int i = 0; i < 2; i++) {
                wmma::load_matrix_sync(ah[i], AsH + (warpM + 16 * i) * LDAs + ks, LDAs);
                if (!FP16)
                    wmma::load_matrix_sync(al[i], AsL + (warpM + 16 * i) * LDAs + ks, LDAs);
            }
            wmma::fragment<wmma::matrix_b, 16, 16, 16, ET, wmma::row_major> bh, bl;
            #pragma unroll
            for (int j = 0; j < 2; j++) {
                wmma::load_matrix_sync(bh, BsH + ks * LDBNs + warpN + 16 * j, LDBNs);
                if (!FP16)
                    wmma::load_matrix_sync(bl, BsL + ks * LDBNs + warpN + 16 * j, LDBNs);
                #pragma unroll
                for (int i = 0; i < 2; i++) {
                    wmma::mma_sync(acc[i][j], ah[i], bh, acc[i][j]);
                    if (!FP16) {
                        wmma::mma_sync(acc[i][j], ah[i], bl, acc[i][j]);
                        wmma::mma_sync(acc[i][j], al[i], bh, acc[i][j]);
                    }
                }
            }
        }
    };

    loadRegs(0);
    splitStore(0);
    __syncthreads();
    for (int kt = 0; kt < nk; kt++) {
        if (kt + 1 < nk) loadRegs(kt + 1);
        compute(kt & 1);
        if (kt + 1 < nk) splitStore((kt + 1) & 1);
        __syncthreads();
    }

    #pragma unroll
    for (int i = 0; i < 2; i++)
        #pragma unroll
        for (int j = 0; j < 2; j++)
            wmma::store_matrix_sync(Cs + (warpM + 16 * i) * LDCss + warpN + 16 * j,
                                    acc[i][j], LDCss, wmma::mem_row_major);
    __syncthreads();
    #pragma unroll
    for (int it = 0; it < 8; it++) {
        int idx = it * 128 + tid;
        int row = idx >> 4;
        int c4 = (idx & 15) * 4;
        long gRow;
        if (lists) {
            int pr = prs[row];
            if (pr < 0) continue;
            gRow = pr;
        } else {
            gRow = rowBase + row;
        }
        float4 v = *(float4*)(Cs + row * LDCss + c4);
        int col = colBase + c4;
        v.x *= scale; v.y *= scale; v.z *= scale; v.w *= scale;
        if (bias) {
            v.x += bias[col]; v.y += bias[col + 1];
            v.z += bias[col + 2]; v.w += bias[col + 3];
        }
        if (Res) {
            const float* rp = Res + gRow * ldc + col;
            v.x += rp[0]; v.y += rp[1]; v.z += rp[2]; v.w += rp[3];
        }
        if (relu) {
            v.x = fmaxf(v.x, 0.f); v.y = fmaxf(v.y, 0.f);
            v.z = fmaxf(v.z, 0.f); v.w = fmaxf(v.w, 0.f);
        }
        if constexpr (CH16) {
            __half2 h0 = __floats2half2_rn(v.x, v.y);
            __half2 h1 = __floats2half2_rn(v.z, v.w);
            *(uint2*)(C + gRow * ldc + col) =
                make_uint2(*(uint32_t*)&h0, *(uint32_t*)&h1);
        } else {
            *(float4*)(C + gRow * ldc + col) = v;
        }
        if constexpr (XFW) {
            // dual-write to g_xf: token gRow = bb*S+s, sub-token head h = col>>7
            int bb = (int)(gRow >> 10), s = (int)(gRow & 1023);
            int h = col >> 7, cc = col & 127;
            long t = ((long)(bb * HMOE + h) * S + s);
            *(float4*)(g_xf + t * HD + cc) = v;
        }
    }
}

// ---------------- QKV weight/bias concat + zero both gate counts --------
__global__ void concat_qkv(const float* __restrict__ wq, const float* __restrict__ wk,
                           const float* __restrict__ wv, const float* __restrict__ bq,
                           const float* __restrict__ bk, const float* __restrict__ bv)
{
    int i = blockIdx.x * blockDim.x + threadIdx.x;   // D*D/4 per weight
    if (i < D * D / 4) {
        int row = i / (D / 4), c4 = (i % (D / 4)) * 4;
        float4* dst = (float4*)(g_wqkv + (long)row * D3);
        dst[c4 / 4]             = *(const float4*)(wq + (long)row * D + c4);
        dst[(D + c4) / 4]       = *(const float4*)(wk + (long)row * D + c4);
        dst[(2 * D + c4) / 4]   = *(const float4*)(wv + (long)row * D + c4);
    }
    if (i < D) {
        g_bqkv[i] = bq[i];
        g_bqkv[D + i] = bk[i];
        g_bqkv[2 * D + i] = bv[i];
    }
    if (i < 2 * E) g_counts[i] = 0;
}

// ---------------- gate + softmax + top-2 + scatter ----------------
template <int KD>
__global__ void gate_topk(
    const float* __restrict__ X, const float* __restrict__ GW,
    const float* __restrict__ GB, float* __restrict__ tw,
    int* __restrict__ lists, int* __restrict__ counts, int cap, int T)
{
    int warp = (blockIdx.x * blockDim.x + threadIdx.x) >> 5;
    int lane = threadIdx.x & 31;
    if (warp >= T) return;
    const float* x = X + (long)warp * KD;
    float xv[KD / 32];
#pragma unroll
    for (int i = 0; i < KD / 32; i++) xv[i] = x[lane + 32 * i];
    float p[E] = {0.f, 0.f, 0.f, 0.f, 0.f, 0.f, 0.f, 0.f};
#pragma unroll
    for (int i = 0; i < KD / 32; i++) {
        float xvi = xv[i];
        const float4* g = (const float4*)(GW + (long)(lane + 32 * i) * E);
        float4 a = g[0], b4 = g[1];
        p[0] += xvi * a.x;  p[1] += xvi * a.y;
        p[2] += xvi * a.z;  p[3] += xvi * a.w;
        p[4] += xvi * b4.x; p[5] += xvi * b4.y;
        p[6] += xvi * b4.z; p[7] += xvi * b4.w;
    }
#pragma unroll
    for (int e = 0; e < E; e++) {
#pragma unroll
        for (int o = 16; o > 0; o >>= 1) p[e] += __shfl_xor_sync(0xffffffffu, p[e], o);
        p[e] += GB[e];
    }
    float m = p[0];
#pragma unroll
    for (int e = 1; e < E; e++) m = fmaxf(m, p[e]);
    float sum = 0.f;
#pragma unroll
    for (int e = 0; e < E; e++) { p[e] = expf(p[e] - m); sum += p[e]; }
    float inv = 1.f / sum;
#pragma unroll
    for (int e = 0; e < E; e++) p[e] *= inv;
    float v0 = -1e30f; int i0 = 0;
#pragma unroll
    for (int e = 0; e < E; e++) if (p[e] > v0) { v0 = p[e]; i0 = e; }
    float v1 = -1e30f; int i1 = 0;
#pragma unroll
    for (int e = 0; e < E; e++) if (e != i0 && p[e] > v1) { v1 = p[e]; i1 = e; }
    float e0 = expf(v0), e1 = expf(v1);
    float wi = 1.f / (e0 + e1);
    if (lane == 0) {
        tw[warp * 2 + 0] = e0 * wi;
        tw[warp * 2 + 1] = e1 * wi;
        int pos0 = atomicAdd(&counts[i0], 1);
        lists[i0 * cap + pos0] = warp * 2;
        int pos1 = atomicAdd(&counts[i1], 1);
        lists[i1 * cap + pos1] = warp * 2 + 1;
    }
}

// ---------------- layernorm (D=512, block=256) ----------------
__global__ void layernorm_k(const float* __restrict__ X,
                            const float* __restrict__ w,
                            const float* __restrict__ b,
                            float* __restrict__ Y)
{
    int row = blockIdx.x;
    const float* x = X + (long)row * D;
    float* y = Y + (long)row * D;
    int tid = threadIdx.x;
    float x0 = x[tid], x1 = x[tid + 256];
    __shared__ float red[256];
    red[tid] = x0 + x1;
    __syncthreads();
    for (int o = 128; o > 0; o >>= 1) { if (tid < o) red[tid] += red[tid + o]; __syncthreads(); }
    float mu = red[0] * (1.f / D);
    __syncthreads();
    float d0 = x0 - mu, d1 = x1 - mu;
    red[tid] = d0 * d0 + d1 * d1;
    __syncthreads();
    for (int o = 128; o > 0; o >>= 1) { if (tid < o) red[tid] += red[tid + o]; __syncthreads(); }
    float rs = rsqrtf(red[0] * (1.f / D) + 1e-12f);
    y[tid]       = d0 * rs * w[tid]       + b[tid];
    y[tid + 256] = d1 * rs * w[tid + 256] + b[tid + 256];
}

// ---------------- row softmax on half scores ----------------
__global__ void softmax_rows_h(__half* __restrict__ Sm)
{
    __half* s = Sm + (long)blockIdx.x * S;
    int tid = threadIdx.x;
    float v[4];
#pragma unroll
    for (int i = 0; i < 4; i++) v[i] = __half2float(s[tid + 256 * i]);
    __shared__ float red[256];
    float m = fmaxf(fmaxf(v[0], v[1]), fmaxf(v[2], v[3]));
    red[tid] = m;
    __syncthreads();
    for (int o = 128; o > 0; o >>= 1) { if (tid < o) red[tid] = fmaxf(red[tid], red[tid + o]); __syncthreads(); }
    m = red[0];
    __syncthreads();
    float t = 0.f;
#pragma unroll
    for (int i = 0; i < 4; i++) { v[i] = expf(v[i] - m); t += v[i]; }
    red[tid] = t;
    __syncthreads();
    for (int o = 128; o > 0; o >>= 1) { if (tid < o) red[tid] += red[tid + o]; __syncthreads(); }
    float inv = 1.f / red[0];
#pragma unroll
    for (int i = 0; i < 4; i++) s[tid + 256 * i] = __float2half(v[i] * inv);
}

// ---------------- small elementwise kernels ----------------
__global__ void combine_local()
{
    int idx = blockIdx.x * blockDim.x + threadIdx.x;
    int t = idx >> 7, c = idx & 127;
    float v = g_xf[idx]
            + g_tw[2 * t]     * g_po[(long)(2 * t) * HD + c]
            + g_tw[2 * t + 1] * g_po[(long)(2 * t + 1) * HD + c];
    int bb = t >> 12, h = (t >> 10) & 3, s = t & 1023;
    g_buf1[((long)(bb * S + s)) * D + h * HD + c] = v;
}

__global__ void final_combine(float* __restrict__ out)
{
    int idx = blockIdx.x * blockDim.x + threadIdx.x;
    int t = idx >> 9, c = idx & 511;
    out[idx] = g_x1[idx]
             + g_tw[2 * t]     * g_po[(long)(2 * t) * D + c]
             + g_tw[2 * t + 1] * g_po[(long)(2 * t + 1) * D + c];
}

// ---------------- launch ----------------
extern "C" void kernel_launch(void* const* d_in, const int* in_sizes, int n_in,
                              void* d_out, int out_size)
{
    const float* x       = (const float*)d_in[0];
    const float* pre_w   = (const float*)d_in[1];
    const float* pre_b   = (const float*)d_in[2];
    const float* l_gw    = (const float*)d_in[3];
    const float* l_gb    = (const float*)d_in[4];
    const float* l_w1    = (const float*)d_in[5];
    const float* l_b1    = (const float*)d_in[6];
    const float* l_w2    = (const float*)d_in[7];
    const float* l_b2    = (const float*)d_in[8];
    const float* align_w = (const float*)d_in[9];
    const float* align_b = (const float*)d_in[10];
    const float* ln1_w   = (const float*)d_in[11];
    const float* ln1_b   = (const float*)d_in[12];
    const float* wq      = (const float*)d_in[13];
    const float* bq      = (const float*)d_in[14];
    const float* wk      = (const float*)d_in[15];
    const float* bk      = (const float*)d_in[16];
    const float* wv      = (const float*)d_in[17];
    const float* bv      = (const float*)d_in[18];
    const float* wo      = (const float*)d_in[19];
    const float* bo      = (const float*)d_in[20];
    const float* ln2_w   = (const float*)d_in[21];
    const float* ln2_b   = (const float*)d_in[22];
    const float* g_gw    = (const float*)d_in[23];
    const float* g_gb    = (const float*)d_in[24];
    const float* gw1     = (const float*)d_in[25];
    const float* gb1     = (const float*)d_in[26];
    const float* gw2     = (const float*)d_in[27];
    const float* gb2     = (const float*)d_in[28];
    float* out = (float*)d_out;

    float *xp, *xf, *po, *buf1, *xl, *xn, *QKV, *O, *x1, *x2, *tw, *wqkv, *bqkv;
    __half *H, *Sch;
    int *lists, *counts;
    cudaGetSymbolAddress((void**)&xp, g_xp);
    cudaGetSymbolAddress((void**)&xf, g_xf);
    cudaGetSymbolAddress((void**)&H, g_H);
    cudaGetSymbolAddress((void**)&po, g_po);
    cudaGetSymbolAddress((void**)&buf1, g_buf1);
    cudaGetSymbolAddress((void**)&xl, g_xl);
    cudaGetSymbolAddress((void**)&xn, g_xn);
    cudaGetSymbolAddress((void**)&QKV, g_QKV);
    cudaGetSymbolAddress((void**)&Sch, g_Sch);
    cudaGetSymbolAddress((void**)&O, g_O);
    cudaGetSymbolAddress((void**)&x1, g_x1);
    cudaGetSymbolAddress((void**)&x2, g_x2);
    cudaGetSymbolAddress((void**)&tw, g_tw);
    cudaGetSymbolAddress((void**)&lists, g_lists);
    cudaGetSymbolAddress((void**)&counts, g_counts);
    cudaGetSymbolAddress((void**)&wqkv, g_wqkv);
    cudaGetSymbolAddress((void**)&bqkv, g_bqkv);

    cudaFuncSetAttribute(wm_gemm<1,1,0,0,1>, cudaFuncAttributeMaxDynamicSharedMemorySize, SMEM_BIG_NT_F16);
    cudaFuncSetAttribute(wm_gemm<0,1,0,0,1>, cudaFuncAttributeMaxDynamicSharedMemorySize, SMEM_BIG_NN_F16);
    cudaFuncSetAttribute(wm_gemm_s<0,0,0,0,1>, cudaFuncAttributeMaxDynamicSharedMemorySize, SMEM_S_SPLIT);
    cudaFuncSetAttribute(wm_gemm_s<1,0,0,0,0>, cudaFuncAttributeMaxDynamicSharedMemorySize, SMEM_S_F16);
    cudaFuncSetAttribute(wm_gemm_s<1,1,0,0,0>, cudaFuncAttributeMaxDynamicSharedMemorySize, SMEM_S_F16);

    const float rscale = 0.08838834764831845f;  // 1/sqrt(128)

    // 0. concat QKV weights + biases; zero both gate count arrays
    concat_qkv<<<(D * D / 4 + 255) / 256, 256>>>(wq, wk, wv, bq, bk, bv);

    // 1. xp = x @ pre_w + pre_b (split-bf16, dual-writes g_xf; feeds gate)
    wm_gemm_s<0,0,0,0,1><<<dim3(TOK / BMs, D / BNs, 1), 128, SMEM_S_SPLIT>>>(
        x, D, 0, 0, pre_w, D, 0, 0, pre_b, 0, nullptr,
        xp, D, 0, 0, D, D, 1, 1.f, 0, nullptr, 0, nullptr, 0);

    // 3-4. local gate + top2 (counts slot 0)
    gate_topk<HD><<<LTOK / 4, 128>>>(xf, l_gw, l_gb, tw, lists, counts, CAP, LTOK);

    // 5. H = relu(xf @ l_w1 + b1)  (fp16 compute, C half, big)
    wm_gemm<0,1,0,0,1><<<dim3(LPAIRS / BM, HID / BN, E), 256, SMEM_BIG_NN_F16>>>(
        xf, HD, 0, 0, l_w1, HID, 0, (long)HD * HID, l_b1, HID, nullptr,
        H, HID, 0, 0, HID, HD, E, 1.f, 1, lists, CAP, counts, 1);

    // 6. po = H @ l_w2 + b2  (small: 512 CTAs; A half)
    wm_gemm_s<1,1,0,0,0><<<dim3(LPAIRS / BMs, HD / BNs, E), 128, SMEM_S_F16>>>(
        H, HID, 0, 0, l_w2, HD, 0, (long)HID * HD, l_b2, HD, nullptr,
        po, HD, 0, 0, HD, HID, E, 1.f, 0, lists, CAP, counts, 0);

    // 7. xf + weighted expert out -> [b,s,d]
    combine_local<<<LTOK * HD / 256, 256>>>();

    // 8. align projection (fp16)
    wm_gemm_s<1,0,0,0,0><<<dim3(TOK / BMs, D / BNs, 1), 128, SMEM_S_F16>>>(
        buf1, D, 0, 0, align_w, D, 0, 0, align_b, 0, nullptr,
        xl, D, 0, 0, D, D, 1, 1.f, 0, nullptr, 0, nullptr, 0);

    // 9. ln1
    layernorm_k<<<TOK, 256>>>(xl, ln1_w, ln1_b, xn);

    // 10. fused QKV projection (768 CTAs)
    wm_gemm_s<1,0,0,0,0><<<dim3(TOK / BMs, D3 / BNs, 1), 128, SMEM_S_F16>>>(
        xn, D, 0, 0, wqkv, D3, 0, 0, bqkv, 0, nullptr,
        QKV, D3, 0, 0, D3, D, 1, 1.f, 0, nullptr, 0, nullptr, 0);

    // 13. scores = Q @ K^T / sqrt(DK)  (NT fp16, C half)
    wm_gemm<1,1,0,0,1><<<dim3(S / BM, S / BN, Bsz * AH), 256, SMEM_BIG_NT_F16>>>(
        QKV, D3, (long)S * D3, DK, QKV + D, D3, (long)S * D3, DK, nullptr, 0, nullptr,
        Sch, S, (long)AH * S * S, (long)S * S,
        S, DK, AH, rscale, 0, nullptr, 0, nullptr, 0);

    // 14. softmax rows (half)
    softmax_rows_h<<<Bsz * AH * S, 256>>>(Sch);

    // 15. O = P @ V  (A half)
    wm_gemm_s<1,1,0,0,0><<<dim3(S / BMs, DK / BNs, Bsz * AH), 128, SMEM_S_F16>>>(
        Sch, S, (long)AH * S * S, (long)S * S,
        QKV + 2 * D, D3, (long)S * D3, DK, nullptr, 0, nullptr,
        O, D, (long)S * D, DK, DK, S, AH, 1.f, 0, nullptr, 0, nullptr, 0);

    // 16. x1 = x + O @ wo + bo  (fp16)
    wm_gemm_s<1,0,0,0,0><<<dim3(TOK / BMs, D / BNs, 1), 128, SMEM_S_F16>>>(
        O, D, 0, 0, wo, D, 0, 0, bo, 0, x,
        x1, D, 0, 0, D, D, 1, 1.f, 0, nullptr, 0, nullptr, 0);

    // 17. ln2
    layernorm_k<<<TOK, 256>>>(x1, ln2_w, ln2_b, x2);

    // 18-19. global gate + top2 (counts slot 1)
    gate_topk<D><<<TOK / 4, 128>>>(x2, g_gw, g_gb, tw, lists, counts + E, CAP, TOK);

    // 20. H = relu(x2 @ gw1 + b1)  (fp16 compute, C half, big)
    wm_gemm<0,1,0,0,1><<<dim3(GPAIRS / BM, HID / BN, E), 256, SMEM_BIG_NN_F16>>>(
        x2, D, 0, 0, gw1, HID, 0, (long)D * HID, gb1, HID, nullptr,
        H, HID, 0, 0, HID, D, E, 1.f, 1, lists, CAP, counts + E, 1);

    // 21. po = H @ gw2 + b2  (small: ~512 CTAs; A half)
    wm_gemm_s<1,1,0,0,0><<<dim3(GPAIRS / BMs, D / BNs, E), 128, SMEM_S_F16>>>(
        H, HID, 0, 0, gw2, D, 0, (long)HID * D, gb2, D, nullptr,
        po, D, 0, 0, D, HID, E, 1.f, 0, lists, CAP, counts + E, 0);

    // 22. out = x1 + weighted expert out
    final_combine<<<TOK * D / 256, 256>>>(out);
}